// round 4
// baseline (speedup 1.0000x reference)
#include <cuda_runtime.h>
#include <math.h>

#define NN   50000
#define EE   800000
#define ENE  (NN+EE)
#define OBSD 256
#define HD   128
#define GD   1024
#define AD   10

// ---------------- scratch (static device globals; no allocation) ----------------
__device__ __align__(16) float g_x[NN*HD];          // tanh embedding
__device__ __align__(16) float g_xlr[NN*2*HD];      // [xl | xr] per node
__device__ __align__(16) float g_intra[NN*HD];
__device__ __align__(16) float g_hid[NN*2*HD];      // [actor_hidden | value_hidden]
__device__ __align__(16) float g_es[ENE];           // CSR-ordered edge scores
__device__ __align__(16) int   g_srcs[ENE];         // CSR-ordered edge sources
__device__ int   g_cnt[NN];
__device__ int   g_cur[NN];
__device__ int   g_off[NN+1];
__device__ __align__(16) float g_c[GD*HD];
__device__ __align__(16) float g_qkv[GD*3*HD];
__device__ __align__(16) float g_sc[4*GD*GD];
__device__ __align__(16) float g_o[GD*HD];
__device__ __align__(16) float g_t1[GD*HD];
__device__ __align__(16) float g_h1[GD*HD];
__device__ __align__(16) float g_f[GD*HD];
__device__ __align__(16) float g_gobs[GD*HD];

__device__ __forceinline__ float lrelu(float x){ return x > 0.f ? x : 0.2f*x; }

// ---------------- generic tiled SGEMM: C = act(A@B + bias) ----------------
// AMODE 0: A[row*lda + k]
// AMODE 1: "after" gather: k<HD -> A[gidx[row]*HD+k], else Aalt[row*HD+k-HD]
// BMODE 0: B[k*ldbk + col*ldbn]
// BMODE 1: col<HD -> B[k*HD+col], else B2[k*HD+col-HD]; bias likewise split
// ACT: 0 none, 1 tanh, 2 relu.  grid.z batching via element strides zA/zB/zC.
template<int AMODE,int BMODE,int ACT>
__global__ __launch_bounds__(256) void k_sgemm(
    const float* __restrict__ A, const float* __restrict__ Aalt, const int* __restrict__ gidx,
    const float* __restrict__ B, const float* __restrict__ B2,
    const float* __restrict__ bias, const float* __restrict__ bias2,
    float* __restrict__ C,
    int M, int N, int K, int lda, int ldbk, int ldbn, int ldc,
    long zA, long zB, long zC)
{
    const int BM=64, BN=64, BK=16;
    __shared__ float As[BK][BM+4];
    __shared__ float Bs[BK][BN+4];
    A += (long)blockIdx.z * zA;
    B += (long)blockIdx.z * zB;
    C += (long)blockIdx.z * zC;
    int bm = blockIdx.x*BM, bn = blockIdx.y*BN;
    int tid = threadIdx.x;
    int tx = tid & 15, ty = tid >> 4;
    float acc[4][4];
    #pragma unroll
    for (int i=0;i<4;i++)
        #pragma unroll
        for (int j=0;j<4;j++) acc[i][j]=0.f;

    for (int k0=0;k0<K;k0+=BK){
        #pragma unroll
        for (int t=0;t<4;t++){
            int i = tid + t*256;
            // A tile: m = i/16, kk = i%16 -> coalesced along k
            int m = i >> 4, kk = i & 15;
            int row = bm + m, k = k0 + kk;
            float v = 0.f;
            if (row < M && k < K){
                if (AMODE==0) v = A[(long)row*lda + k];
                else          v = (k < HD) ? A[(long)gidx[row]*HD + k]
                                           : Aalt[(long)row*HD + (k-HD)];
            }
            As[kk][m] = v;
            // B tile: kk2 = i/64, n = i%64 -> coalesced along col (when ldbn==1)
            int kk2 = i >> 6, n = i & 63;
            int col = bn + n, k2 = k0 + kk2;
            float w = 0.f;
            if (col < N && k2 < K){
                if (BMODE==0) w = B[(long)k2*ldbk + (long)col*ldbn];
                else          w = (col < HD) ? B[(long)k2*HD + col]
                                             : B2[(long)k2*HD + (col-HD)];
            }
            Bs[kk2][n] = w;
        }
        __syncthreads();
        #pragma unroll
        for (int kk=0;kk<BK;kk++){
            float a0=As[kk][ty*4+0], a1=As[kk][ty*4+1], a2=As[kk][ty*4+2], a3=As[kk][ty*4+3];
            float b0=Bs[kk][tx*4+0], b1=Bs[kk][tx*4+1], b2=Bs[kk][tx*4+2], b3=Bs[kk][tx*4+3];
            acc[0][0]+=a0*b0; acc[0][1]+=a0*b1; acc[0][2]+=a0*b2; acc[0][3]+=a0*b3;
            acc[1][0]+=a1*b0; acc[1][1]+=a1*b1; acc[1][2]+=a1*b2; acc[1][3]+=a1*b3;
            acc[2][0]+=a2*b0; acc[2][1]+=a2*b1; acc[2][2]+=a2*b2; acc[2][3]+=a2*b3;
            acc[3][0]+=a3*b0; acc[3][1]+=a3*b1; acc[3][2]+=a3*b2; acc[3][3]+=a3*b3;
        }
        __syncthreads();
    }
    #pragma unroll
    for (int i=0;i<4;i++){
        int row = bm + ty*4 + i;
        if (row >= M) continue;
        #pragma unroll
        for (int j=0;j<4;j++){
            int col = bn + tx*4 + j;
            if (col >= N) continue;
            float v = acc[i][j];
            if (BMODE==1){ if (bias) v += (col < HD) ? bias[col] : bias2[col-HD]; }
            else if (bias)           v += bias[col];
            if (ACT==1) v = tanhf(v);
            if (ACT==2) v = fmaxf(v, 0.f);
            C[(long)row*ldc + col] = v;
        }
    }
}

// ---------------- GAT pipeline ----------------
__global__ void k_init(){
    int i = blockIdx.x*blockDim.x + threadIdx.x;
    if (i < NN){ g_cnt[i] = 1; g_cur[i] = 0; }   // 1 = self loop
    if (i == 0) g_off[NN] = ENE;
}

__global__ void k_count(const int* __restrict__ ei){
    int i = blockIdx.x*blockDim.x + threadIdx.x;
    if (i < EE) atomicAdd(&g_cnt[ei[EE+i]], 1);
}

__global__ void k_scan(){
    __shared__ int sh[1024];
    int t = threadIdx.x;
    const int chunk = (NN + 1023) / 1024;   // 49
    int base = t * chunk;
    int s = 0;
    for (int i=0;i<chunk;i++){ int idx = base+i; if (idx < NN) s += g_cnt[idx]; }
    sh[t] = s; __syncthreads();
    for (int d=1; d<1024; d<<=1){
        int v = (t >= d) ? sh[t-d] : 0;
        __syncthreads();
        sh[t] += v;
        __syncthreads();
    }
    int run = sh[t] - s;   // exclusive prefix
    for (int i=0;i<chunk;i++){
        int idx = base+i;
        if (idx < NN){ g_off[idx] = run; run += g_cnt[idx]; }
    }
}

// warp per edge: e = leakyrelu(xl[src]+xr[dst]) . att ; scatter into CSR slot
__global__ void k_edge(const int* __restrict__ ei, const float* __restrict__ att){
    int w = blockIdx.x*(blockDim.x>>5) + (threadIdx.x>>5);
    if (w >= ENE) return;
    int lane = threadIdx.x & 31;
    int src, dst;
    if (w < EE){ src = ei[w]; dst = ei[EE+w]; } else { src = dst = w - EE; }
    float4 a = *(const float4*)(g_xlr + (long)src*256 + lane*4);
    float4 b = *(const float4*)(g_xlr + (long)dst*256 + 128 + lane*4);
    float4 t = *(const float4*)(att + lane*4);
    float e = lrelu(a.x+b.x)*t.x + lrelu(a.y+b.y)*t.y + lrelu(a.z+b.z)*t.z + lrelu(a.w+b.w)*t.w;
    #pragma unroll
    for (int o=16;o;o>>=1) e += __shfl_xor_sync(0xffffffffu, e, o);
    if (lane == 0){
        int pos = g_off[dst] + atomicAdd(&g_cur[dst], 1);
        g_es[pos] = e;
        g_srcs[pos] = src;
    }
}

// warp per node: segment softmax + weighted aggregate of xl[src], tanh(+bias)
__global__ void k_agg(const float* __restrict__ gbias){
    int n = blockIdx.x*(blockDim.x>>5) + (threadIdx.x>>5);
    if (n >= NN) return;
    int lane = threadIdx.x & 31;
    int s0 = g_off[n], s1 = g_off[n+1];
    float m = -1e30f;
    for (int j=s0+lane; j<s1; j+=32) m = fmaxf(m, g_es[j]);
    #pragma unroll
    for (int o=16;o;o>>=1) m = fmaxf(m, __shfl_xor_sync(0xffffffffu, m, o));
    float s = 0.f;
    float4 acc = make_float4(0.f,0.f,0.f,0.f);
    for (int j=s0; j<s1; j++){
        float w = expf(g_es[j] - m);     // broadcast load, same for all lanes
        int sr = g_srcs[j];
        s += w;
        float4 xv = *(const float4*)(g_xlr + (long)sr*256 + lane*4);
        acc.x += w*xv.x; acc.y += w*xv.y; acc.z += w*xv.z; acc.w += w*xv.w;
    }
    float inv = 1.f / s;
    float4 bv = *(const float4*)(gbias + lane*4);
    float* op = g_intra + (long)n*HD + lane*4;
    op[0] = tanhf(acc.x*inv + bv.x);
    op[1] = tanhf(acc.y*inv + bv.y);
    op[2] = tanhf(acc.z*inv + bv.z);
    op[3] = tanhf(acc.w*inv + bv.w);
}

// ---------------- transformer helpers ----------------
__global__ void k_gather_c(const int* __restrict__ cn){
    int i = blockIdx.x*blockDim.x + threadIdx.x;
    if (i < GD*HD) g_c[i] = g_intra[(long)cn[i>>7]*HD + (i & 127)];
}

__global__ void k_softmax(){
    int r = blockIdx.x*(blockDim.x>>5) + (threadIdx.x>>5);
    if (r >= 4*GD) return;
    int lane = threadIdx.x & 31;
    float* p = g_sc + (long)r*GD;
    const float scale = 0.17677669529663687f;   // 1/sqrt(32)
    float v[32];
    float m = -1e30f;
    #pragma unroll
    for (int i=0;i<32;i++){ v[i] = p[lane + 32*i] * scale; m = fmaxf(m, v[i]); }
    #pragma unroll
    for (int o=16;o;o>>=1) m = fmaxf(m, __shfl_xor_sync(0xffffffffu, m, o));
    float s = 0.f;
    #pragma unroll
    for (int i=0;i<32;i++){ v[i] = expf(v[i]-m); s += v[i]; }
    #pragma unroll
    for (int o=16;o;o>>=1) s += __shfl_xor_sync(0xffffffffu, s, o);
    float inv = 1.f / s;
    #pragma unroll
    for (int i=0;i<32;i++) p[lane + 32*i] = v[i]*inv;
}

// out = [tanh]( LN(x + y) * g + b ), warp per row of 128
template<int TANH>
__global__ void k_ln(const float* __restrict__ x, const float* __restrict__ y,
                     const float* __restrict__ g, const float* __restrict__ b,
                     float* __restrict__ out, int rows){
    int r = blockIdx.x*(blockDim.x>>5) + (threadIdx.x>>5);
    if (r >= rows) return;
    int lane = threadIdx.x & 31;
    float4 xv = *(const float4*)(x + (long)r*HD + lane*4);
    float4 yv = *(const float4*)(y + (long)r*HD + lane*4);
    float v0 = xv.x+yv.x, v1 = xv.y+yv.y, v2 = xv.z+yv.z, v3 = xv.w+yv.w;
    float s = v0+v1+v2+v3;
    #pragma unroll
    for (int o=16;o;o>>=1) s += __shfl_xor_sync(0xffffffffu, s, o);
    float mu = s * (1.f/128.f);
    float d0=v0-mu, d1=v1-mu, d2=v2-mu, d3=v3-mu;
    float q = d0*d0 + d1*d1 + d2*d2 + d3*d3;
    #pragma unroll
    for (int o=16;o;o>>=1) q += __shfl_xor_sync(0xffffffffu, q, o);
    float rs = rsqrtf(q * (1.f/128.f) + 1e-5f);
    float4 gv = *(const float4*)(g + lane*4);
    float4 bv = *(const float4*)(b + lane*4);
    float o0 = d0*rs*gv.x + bv.x;
    float o1 = d1*rs*gv.y + bv.y;
    float o2 = d2*rs*gv.z + bv.z;
    float o3 = d3*rs*gv.w + bv.w;
    if (TANH){ o0=tanhf(o0); o1=tanhf(o1); o2=tanhf(o2); o3=tanhf(o3); }
    *(float4*)(out + (long)r*HD + lane*4) = make_float4(o0,o1,o2,o3);
}

// ---------------- final heads: warp per node ----------------
__global__ void k_heads(const float* __restrict__ aw2, const float* __restrict__ ab2,
                        const float* __restrict__ vw2, const float* __restrict__ vb2,
                        float* __restrict__ out){
    int n = blockIdx.x*(blockDim.x>>5) + (threadIdx.x>>5);
    if (n >= NN) return;
    int lane = threadIdx.x & 31;
    const float* hp = g_hid + (long)n*256;
    float4 ha = *(const float4*)(hp + lane*4);
    float l[AD];
    #pragma unroll
    for (int j=0;j<AD;j++){
        l[j] = ha.x*aw2[(lane*4+0)*AD+j] + ha.y*aw2[(lane*4+1)*AD+j]
             + ha.z*aw2[(lane*4+2)*AD+j] + ha.w*aw2[(lane*4+3)*AD+j];
    }
    #pragma unroll
    for (int j=0;j<AD;j++)
        #pragma unroll
        for (int o=16;o;o>>=1) l[j] += __shfl_xor_sync(0xffffffffu, l[j], o);
    float4 hv = *(const float4*)(hp + 128 + lane*4);
    float4 wv = *(const float4*)(vw2 + lane*4);
    float v = hv.x*wv.x + hv.y*wv.y + hv.z*wv.z + hv.w*wv.w;
    #pragma unroll
    for (int o=16;o;o>>=1) v += __shfl_xor_sync(0xffffffffu, v, o);
    if (lane == 0){
        float m = -1e30f;
        #pragma unroll
        for (int j=0;j<AD;j++){ l[j] += ab2[j]; m = fmaxf(m, l[j]); }
        float s = 0.f;
        #pragma unroll
        for (int j=0;j<AD;j++) s += expf(l[j]-m);
        float ls = logf(s) + m;
        #pragma unroll
        for (int j=0;j<AD;j++) out[(long)n*AD + j] = l[j] - ls;
        out[(long)NN*AD + n] = v + vb2[0];
    }
}

// ---------------- host ----------------
extern "C" void kernel_launch(void* const* d_in, const int* in_sizes, int n_in,
                              void* d_out, int out_size)
{
    const float* obs  = (const float*)d_in[0];
    const int*   ei   = (const int*)d_in[1];
    const int*   ga   = (const int*)d_in[2];
    const int*   cn   = (const int*)d_in[3];
    const float* embw = (const float*)d_in[4];  const float* embb = (const float*)d_in[5];
    const float* wl   = (const float*)d_in[6];  const float* wr   = (const float*)d_in[7];
    const float* att  = (const float*)d_in[8];  const float* gbias= (const float*)d_in[9];
    const float* ainw = (const float*)d_in[10]; const float* ainb = (const float*)d_in[11];
    const float* aow  = (const float*)d_in[12]; const float* aob  = (const float*)d_in[13];
    const float* ln1g = (const float*)d_in[14]; const float* ln1b = (const float*)d_in[15];
    const float* ln2g = (const float*)d_in[16]; const float* ln2b = (const float*)d_in[17];
    const float* fw1  = (const float*)d_in[18]; const float* fb1  = (const float*)d_in[19];
    const float* fw2  = (const float*)d_in[20]; const float* fb2  = (const float*)d_in[21];
    const float* aw1  = (const float*)d_in[22]; const float* ab1  = (const float*)d_in[23];
    const float* aw2  = (const float*)d_in[24]; const float* ab2  = (const float*)d_in[25];
    const float* vw1  = (const float*)d_in[26]; const float* vb1  = (const float*)d_in[27];
    const float* vw2  = (const float*)d_in[28]; const float* vb2  = (const float*)d_in[29];
    float* out = (float*)d_out;

    void *pv;
    cudaGetSymbolAddress(&pv, g_x);     float* fx    = (float*)pv;
    cudaGetSymbolAddress(&pv, g_xlr);   float* fxlr  = (float*)pv;
    cudaGetSymbolAddress(&pv, g_intra); float* fintra= (float*)pv;
    cudaGetSymbolAddress(&pv, g_hid);   float* fhid  = (float*)pv;
    cudaGetSymbolAddress(&pv, g_c);     float* fc    = (float*)pv;
    cudaGetSymbolAddress(&pv, g_qkv);   float* fqkv  = (float*)pv;
    cudaGetSymbolAddress(&pv, g_sc);    float* fsc   = (float*)pv;
    cudaGetSymbolAddress(&pv, g_o);     float* fo    = (float*)pv;
    cudaGetSymbolAddress(&pv, g_t1);    float* ft1   = (float*)pv;
    cudaGetSymbolAddress(&pv, g_h1);    float* fh1   = (float*)pv;
    cudaGetSymbolAddress(&pv, g_f);     float* ff    = (float*)pv;
    cudaGetSymbolAddress(&pv, g_gobs);  float* fgobs = (float*)pv;

    // CSR build
    k_init <<<(NN+255)/256, 256>>>();
    k_count<<<(EE+255)/256, 256>>>(ei);
    k_scan <<<1, 1024>>>();

    // x = tanh(obs @ emb_w + b)
    dim3 g1((NN+63)/64, (HD+63)/64);
    k_sgemm<0,0,1><<<g1,256>>>(obs,nullptr,nullptr, embw,nullptr, embb,nullptr,
                               fx, NN,HD,OBSD, OBSD,HD,1,HD, 0,0,0);
    // [xl|xr] = x @ [Wl|Wr]
    dim3 g2((NN+63)/64, (2*HD+63)/64);
    k_sgemm<0,1,0><<<g2,256>>>(fx,nullptr,nullptr, wl,wr, nullptr,nullptr,
                               fxlr, NN,2*HD,HD, HD,0,0,2*HD, 0,0,0);
    // edge scores -> CSR, then segment softmax-aggregate
    k_edge<<<(ENE+7)/8, 256>>>(ei, att);
    k_agg <<<(NN+7)/8, 256>>>(gbias);

    // transformer over core nodes
    k_gather_c<<<(GD*HD+255)/256, 256>>>(cn);
    dim3 g3((GD+63)/64, (3*HD+63)/64);
    k_sgemm<0,0,0><<<g3,256>>>(fc,nullptr,nullptr, ainw,nullptr, ainb,nullptr,
                               fqkv, GD,3*HD,HD, HD,3*HD,1,3*HD, 0,0,0);
    // scores[h] = Q_h @ K_h^T   (grid.z = heads)
    dim3 g4((GD+63)/64, (GD+63)/64, 4);
    k_sgemm<0,0,0><<<g4,256>>>(fqkv,nullptr,nullptr, fqkv+HD,nullptr, nullptr,nullptr,
                               fsc, GD,GD,32, 3*HD,1,3*HD,GD, 32,32,(long)GD*GD);
    k_softmax<<<(4*GD+7)/8, 256>>>();
    // o[h] = attn_h @ V_h
    dim3 g5((GD+63)/64, 1, 4);
    k_sgemm<0,0,0><<<g5,256>>>(fsc,nullptr,nullptr, fqkv+2*HD,nullptr, nullptr,nullptr,
                               fo, GD,32,GD, GD,3*HD,1,HD, (long)GD*GD,32,32);
    // out-proj, LN1, FFN, LN2+tanh
    dim3 g6((GD+63)/64, (HD+63)/64);
    k_sgemm<0,0,0><<<g6,256>>>(fo,nullptr,nullptr, aow,nullptr, aob,nullptr,
                               ft1, GD,HD,HD, HD,HD,1,HD, 0,0,0);
    k_ln<0><<<(GD+7)/8, 256>>>(fc, ft1, ln1g, ln1b, fh1, GD);
    k_sgemm<0,0,2><<<g6,256>>>(fh1,nullptr,nullptr, fw1,nullptr, fb1,nullptr,
                               ff, GD,HD,HD, HD,HD,1,HD, 0,0,0);
    k_sgemm<0,0,0><<<g6,256>>>(ff,nullptr,nullptr, fw2,nullptr, fb2,nullptr,
                               ft1, GD,HD,HD, HD,HD,1,HD, 0,0,0);
    k_ln<1><<<(GD+7)/8, 256>>>(fh1, ft1, ln2g, ln2b, fgobs, GD);

    // hidden = tanh( [group_obs[ga] | intra] @ [actor_w1 | value_w1] + bias )
    dim3 g7((NN+63)/64, (2*HD+63)/64);
    k_sgemm<1,1,1><<<g7,256>>>(fgobs, fintra, ga, aw1, vw1, ab1, vb1,
                               fhid, NN,2*HD,2*HD, 0,0,0,2*HD, 0,0,0);
    // final logits + log_softmax + value
    k_heads<<<(NN+7)/8, 256>>>(aw2, ab2, vw2, vb2, out);
}

// round 8
// speedup vs baseline: 1.4408x; 1.4408x over previous
#include <cuda_runtime.h>
#include <math.h>

#define NN   50000
#define EE   800000
#define ENE  (NN+EE)
#define OBSD 256
#define HD   128
#define GD   1024
#define AD   10

// ---------------- scratch (static device globals; no allocation) ----------------
__device__ __align__(16) float g_x[NN*HD];          // tanh embedding
__device__ __align__(16) float g_xlr[NN*2*HD];      // [xl | xr] per node
__device__ __align__(16) float g_intra[NN*HD];
__device__ __align__(16) float g_hid[NN*2*HD];      // [actor_hidden | value_hidden]
__device__ __align__(16) float g_es[ENE];           // CSR-ordered edge scores
__device__ __align__(16) int   g_srcs[ENE];         // CSR-ordered edge sources
__device__ int   g_cnt[NN];
__device__ int   g_cur[NN];
__device__ int   g_off[NN+1];
__device__ __align__(16) float g_c[GD*HD];
__device__ __align__(16) float g_qkv[GD*3*HD];
__device__ __align__(16) float g_sc[4*GD*GD];
__device__ __align__(16) float g_o[GD*HD];
__device__ __align__(16) float g_t1[GD*HD];
__device__ __align__(16) float g_h1[GD*HD];
__device__ __align__(16) float g_f[GD*HD];
__device__ __align__(16) float g_gobs[GD*HD];
__device__ __align__(16) float g_pg[GD*2*HD];       // gobs @ [actor_w1_top | value_w1_top]

__device__ __forceinline__ float lrelu(float x){ return x > 0.f ? x : 0.2f*x; }

// ================= big-tile SGEMM: 128x128 block, 8x8/thread =================
// C[row, bn+col] = epi( A[row,:K] @ B[:,col] + bias[col] (+ PG[gidx[row]*256+bn+col]) )
// B is selected per blockIdx.y (column block of 128): y==0 -> B0/bias0, y==1 -> B1/bias1.
// B layout: B[k*128 + col], fixed ldb=128. EPI: 0 none, 1 tanh, 3 tanh + PG gather add.
template<int EPI>
__global__ __launch_bounds__(256) void k_gemm128(
    const float* __restrict__ A,
    const float* __restrict__ B0, const float* __restrict__ B1,
    const float* __restrict__ bias0, const float* __restrict__ bias1,
    const float* __restrict__ PG, const int* __restrict__ gidx,
    float* __restrict__ C,
    int M, int K, int lda, int ldc)
{
    __shared__ float As[16][132];
    __shared__ float Bs[16][128];
    const float* B    = blockIdx.y ? B1 : B0;
    const float* bias = blockIdx.y ? bias1 : bias0;
    const int bn = blockIdx.y * 128;
    const int bm = blockIdx.x * 128;
    const int tid = threadIdx.x;
    const int tx = tid & 15, ty = tid >> 4;

    const int arow = tid >> 1;
    const int akk  = (tid & 1) * 8;
    const int grow = bm + arow;
    const bool rok = (grow < M);
    const float* Ap = A + (long)grow * lda;

    const int bkk  = tid >> 5;
    const int bcol = (tid & 31) * 4;

    float acc[8][8];
    #pragma unroll
    for (int i=0;i<8;i++)
        #pragma unroll
        for (int j=0;j<8;j++) acc[i][j] = 0.f;

    for (int k0=0; k0<K; k0+=16){
        float4 av0 = make_float4(0,0,0,0), av1 = make_float4(0,0,0,0);
        if (rok){
            av0 = *(const float4*)(Ap + k0 + akk);
            av1 = *(const float4*)(Ap + k0 + akk + 4);
        }
        As[akk+0][arow]=av0.x; As[akk+1][arow]=av0.y; As[akk+2][arow]=av0.z; As[akk+3][arow]=av0.w;
        As[akk+4][arow]=av1.x; As[akk+5][arow]=av1.y; As[akk+6][arow]=av1.z; As[akk+7][arow]=av1.w;
        float4 bv0 = *(const float4*)(B + (long)(k0+bkk  )*128 + bcol);
        float4 bv1 = *(const float4*)(B + (long)(k0+bkk+8)*128 + bcol);
        *(float4*)&Bs[bkk  ][bcol] = bv0;
        *(float4*)&Bs[bkk+8][bcol] = bv1;
        __syncthreads();
        #pragma unroll
        for (int kk=0; kk<16; kk++){
            float4 a0 = *(const float4*)&As[kk][ty*4];
            float4 a1 = *(const float4*)&As[kk][64 + ty*4];
            float4 b0 = *(const float4*)&Bs[kk][tx*4];
            float4 b1 = *(const float4*)&Bs[kk][64 + tx*4];
            float ar[8] = {a0.x,a0.y,a0.z,a0.w,a1.x,a1.y,a1.z,a1.w};
            float br[8] = {b0.x,b0.y,b0.z,b0.w,b1.x,b1.y,b1.z,b1.w};
            #pragma unroll
            for (int i=0;i<8;i++)
                #pragma unroll
                for (int j=0;j<8;j++) acc[i][j] += ar[i]*br[j];
        }
        __syncthreads();
    }

    #pragma unroll
    for (int i=0;i<8;i++){
        int r = bm + ((i<4) ? (ty*4+i) : (64 + ty*4 + i - 4));
        if (r >= M) continue;
        int gi = 0;
        if (EPI==3) gi = gidx[r];
        #pragma unroll
        for (int j=0;j<8;j++){
            int cl = (j<4) ? (tx*4+j) : (64 + tx*4 + j - 4);
            float v = acc[i][j];
            if (bias) v += bias[cl];
            if (EPI==3) v += PG[(long)gi*256 + bn + cl];
            if (EPI==1 || EPI==3) v = tanhf(v);
            C[(long)r*ldc + bn + cl] = v;
        }
    }
}

// ---------------- generic tiled SGEMM (64x64), kept for small/odd shapes ----------------
// BMODE 0: B[k*ldbk + col*ldbn]
// BMODE 1: col<HD -> B[k*HD+col], else B2[k*HD+col-HD]; bias likewise split (null ok)
// ACT: 0 none, 1 tanh, 2 relu.  grid.z batching via element strides zA/zB/zC.
template<int BMODE,int ACT>
__global__ __launch_bounds__(256) void k_sgemm(
    const float* __restrict__ A,
    const float* __restrict__ B, const float* __restrict__ B2,
    const float* __restrict__ bias, const float* __restrict__ bias2,
    float* __restrict__ C,
    int M, int N, int K, int lda, int ldbk, int ldbn, int ldc,
    long zA, long zB, long zC)
{
    const int BM=64, BN=64, BK=16;
    __shared__ float As[BK][BM+4];
    __shared__ float Bs[BK][BN+4];
    A += (long)blockIdx.z * zA;
    B += (long)blockIdx.z * zB;
    C += (long)blockIdx.z * zC;
    int bm = blockIdx.x*BM, bn = blockIdx.y*BN;
    int tid = threadIdx.x;
    int tx = tid & 15, ty = tid >> 4;
    float acc[4][4];
    #pragma unroll
    for (int i=0;i<4;i++)
        #pragma unroll
        for (int j=0;j<4;j++) acc[i][j]=0.f;

    for (int k0=0;k0<K;k0+=BK){
        #pragma unroll
        for (int t=0;t<4;t++){
            int i = tid + t*256;
            int m = i >> 4, kk = i & 15;
            int row = bm + m, k = k0 + kk;
            float v = 0.f;
            if (row < M && k < K) v = A[(long)row*lda + k];
            As[kk][m] = v;
            int kk2 = i >> 6, n = i & 63;
            int col = bn + n, k2 = k0 + kk2;
            float w = 0.f;
            if (col < N && k2 < K){
                if (BMODE==0) w = B[(long)k2*ldbk + (long)col*ldbn];
                else          w = (col < HD) ? B[(long)k2*HD + col]
                                             : B2[(long)k2*HD + (col-HD)];
            }
            Bs[kk2][n] = w;
        }
        __syncthreads();
        #pragma unroll
        for (int kk=0;kk<BK;kk++){
            float a0=As[kk][ty*4+0], a1=As[kk][ty*4+1], a2=As[kk][ty*4+2], a3=As[kk][ty*4+3];
            float b0=Bs[kk][tx*4+0], b1=Bs[kk][tx*4+1], b2=Bs[kk][tx*4+2], b3=Bs[kk][tx*4+3];
            acc[0][0]+=a0*b0; acc[0][1]+=a0*b1; acc[0][2]+=a0*b2; acc[0][3]+=a0*b3;
            acc[1][0]+=a1*b0; acc[1][1]+=a1*b1; acc[1][2]+=a1*b2; acc[1][3]+=a1*b3;
            acc[2][0]+=a2*b0; acc[2][1]+=a2*b1; acc[2][2]+=a2*b2; acc[2][3]+=a2*b3;
            acc[3][0]+=a3*b0; acc[3][1]+=a3*b1; acc[3][2]+=a3*b2; acc[3][3]+=a3*b3;
        }
        __syncthreads();
    }
    #pragma unroll
    for (int i=0;i<4;i++){
        int row = bm + ty*4 + i;
        if (row >= M) continue;
        #pragma unroll
        for (int j=0;j<4;j++){
            int col = bn + tx*4 + j;
            if (col >= N) continue;
            float v = acc[i][j];
            if (BMODE==1){ if (bias) v += (col < HD) ? bias[col] : bias2[col-HD]; }
            else if (bias)           v += bias[col];
            if (ACT==1) v = tanhf(v);
            if (ACT==2) v = fmaxf(v, 0.f);
            C[(long)row*ldc + col] = v;
        }
    }
}

// ---------------- GAT pipeline ----------------
__global__ void k_init(){
    int i = blockIdx.x*blockDim.x + threadIdx.x;
    if (i < NN){ g_cnt[i] = 1; g_cur[i] = 0; }   // 1 = self loop
    if (i == 0) g_off[NN] = ENE;
}

__global__ void k_count(const int* __restrict__ ei){
    int i = blockIdx.x*blockDim.x + threadIdx.x;
    if (i < EE) atomicAdd(&g_cnt[ei[EE+i]], 1);
}

__global__ void k_scan(){
    __shared__ int sh[1024];
    int t = threadIdx.x;
    const int chunk = (NN + 1023) / 1024;   // 49
    int base = t * chunk;
    int s = 0;
    for (int i=0;i<chunk;i++){ int idx = base+i; if (idx < NN) s += g_cnt[idx]; }
    sh[t] = s; __syncthreads();
    for (int d=1; d<1024; d<<=1){
        int v = (t >= d) ? sh[t-d] : 0;
        __syncthreads();
        sh[t] += v;
        __syncthreads();
    }
    int run = sh[t] - s;   // exclusive prefix
    for (int i=0;i<chunk;i++){
        int idx = base+i;
        if (idx < NN){ g_off[idx] = run; run += g_cnt[idx]; }
    }
}

// warp per edge: e = leakyrelu(xl[src]+xr[dst]) . att ; scatter into CSR slot
__global__ void k_edge(const int* __restrict__ ei, const float* __restrict__ att){
    int w = blockIdx.x*(blockDim.x>>5) + (threadIdx.x>>5);
    if (w >= ENE) return;
    int lane = threadIdx.x & 31;
    int src, dst;
    if (w < EE){ src = ei[w]; dst = ei[EE+w]; } else { src = dst = w - EE; }
    float4 a = *(const float4*)(g_xlr + (long)src*256 + lane*4);
    float4 b = *(const float4*)(g_xlr + (long)dst*256 + 128 + lane*4);
    float4 t = *(const float4*)(att + lane*4);
    float e = lrelu(a.x+b.x)*t.x + lrelu(a.y+b.y)*t.y + lrelu(a.z+b.z)*t.z + lrelu(a.w+b.w)*t.w;
    #pragma unroll
    for (int o=16;o;o>>=1) e += __shfl_xor_sync(0xffffffffu, e, o);
    if (lane == 0){
        int pos = g_off[dst] + atomicAdd(&g_cur[dst], 1);
        g_es[pos] = e;
        g_srcs[pos] = src;
    }
}

// warp per node: segment softmax + weighted aggregate of xl[src], tanh(+bias)
__global__ void k_agg(const float* __restrict__ gbias){
    int n = blockIdx.x*(blockDim.x>>5) + (threadIdx.x>>5);
    if (n >= NN) return;
    int lane = threadIdx.x & 31;
    int s0 = g_off[n], s1 = g_off[n+1];
    float m = -1e30f;
    for (int j=s0+lane; j<s1; j+=32) m = fmaxf(m, g_es[j]);
    #pragma unroll
    for (int o=16;o;o>>=1) m = fmaxf(m, __shfl_xor_sync(0xffffffffu, m, o));
    float s = 0.f;
    float4 acc = make_float4(0.f,0.f,0.f,0.f);
    for (int j=s0; j<s1; j++){
        float w = expf(g_es[j] - m);     // broadcast load, same for all lanes
        int sr = g_srcs[j];
        s += w;
        float4 xv = *(const float4*)(g_xlr + (long)sr*256 + lane*4);
        acc.x += w*xv.x; acc.y += w*xv.y; acc.z += w*xv.z; acc.w += w*xv.w;
    }
    float inv = 1.f / s;
    float4 bv = *(const float4*)(gbias + lane*4);
    float* op = g_intra + (long)n*HD + lane*4;
    op[0] = tanhf(acc.x*inv + bv.x);
    op[1] = tanhf(acc.y*inv + bv.y);
    op[2] = tanhf(acc.z*inv + bv.z);
    op[3] = tanhf(acc.w*inv + bv.w);
}

// ---------------- transformer helpers ----------------
__global__ void k_gather_c(const int* __restrict__ cn){
    int i = blockIdx.x*blockDim.x + threadIdx.x;
    if (i < GD*HD) g_c[i] = g_intra[(long)cn[i>>7]*HD + (i & 127)];
}

__global__ void k_softmax(){
    int r = blockIdx.x*(blockDim.x>>5) + (threadIdx.x>>5);
    if (r >= 4*GD) return;
    int lane = threadIdx.x & 31;
    float* p = g_sc + (long)r*GD;
    const float scale = 0.17677669529663687f;   // 1/sqrt(32)
    float v[32];
    float m = -1e30f;
    #pragma unroll
    for (int i=0;i<32;i++){ v[i] = p[lane + 32*i] * scale; m = fmaxf(m, v[i]); }
    #pragma unroll
    for (int o=16;o;o>>=1) m = fmaxf(m, __shfl_xor_sync(0xffffffffu, m, o));
    float s = 0.f;
    #pragma unroll
    for (int i=0;i<32;i++){ v[i] = expf(v[i]-m); s += v[i]; }
    #pragma unroll
    for (int o=16;o;o>>=1) s += __shfl_xor_sync(0xffffffffu, s, o);
    float inv = 1.f / s;
    #pragma unroll
    for (int i=0;i<32;i++) p[lane + 32*i] = v[i]*inv;
}

// out = [tanh]( LN(x + y) * g + b ), warp per row of 128
template<int TANH>
__global__ void k_ln(const float* __restrict__ x, const float* __restrict__ y,
                     const float* __restrict__ g, const float* __restrict__ b,
                     float* __restrict__ out, int rows){
    int r = blockIdx.x*(blockDim.x>>5) + (threadIdx.x>>5);
    if (r >= rows) return;
    int lane = threadIdx.x & 31;
    float4 xv = *(const float4*)(x + (long)r*HD + lane*4);
    float4 yv = *(const float4*)(y + (long)r*HD + lane*4);
    float v0 = xv.x+yv.x, v1 = xv.y+yv.y, v2 = xv.z+yv.z, v3 = xv.w+yv.w;
    float s = v0+v1+v2+v3;
    #pragma unroll
    for (int o=16;o;o>>=1) s += __shfl_xor_sync(0xffffffffu, s, o);
    float mu = s * (1.f/128.f);
    float d0=v0-mu, d1=v1-mu, d2=v2-mu, d3=v3-mu;
    float q = d0*d0 + d1*d1 + d2*d2 + d3*d3;
    #pragma unroll
    for (int o=16;o;o>>=1) q += __shfl_xor_sync(0xffffffffu, q, o);
    float rs = rsqrtf(q * (1.f/128.f) + 1e-5f);
    float4 gv = *(const float4*)(g + lane*4);
    float4 bv = *(const float4*)(b + lane*4);
    float o0 = d0*rs*gv.x + bv.x;
    float o1 = d1*rs*gv.y + bv.y;
    float o2 = d2*rs*gv.z + bv.z;
    float o3 = d3*rs*gv.w + bv.w;
    if (TANH){ o0=tanhf(o0); o1=tanhf(o1); o2=tanhf(o2); o3=tanhf(o3); }
    *(float4*)(out + (long)r*HD + lane*4) = make_float4(o0,o1,o2,o3);
}

// ---------------- final heads: warp per node ----------------
__global__ void k_heads(const float* __restrict__ aw2, const float* __restrict__ ab2,
                        const float* __restrict__ vw2, const float* __restrict__ vb2,
                        float* __restrict__ out){
    int n = blockIdx.x*(blockDim.x>>5) + (threadIdx.x>>5);
    if (n >= NN) return;
    int lane = threadIdx.x & 31;
    const float* hp = g_hid + (long)n*256;
    float4 ha = *(const float4*)(hp + lane*4);
    float l[AD];
    #pragma unroll
    for (int j=0;j<AD;j++){
        l[j] = ha.x*aw2[(lane*4+0)*AD+j] + ha.y*aw2[(lane*4+1)*AD+j]
             + ha.z*aw2[(lane*4+2)*AD+j] + ha.w*aw2[(lane*4+3)*AD+j];
    }
    #pragma unroll
    for (int j=0;j<AD;j++)
        #pragma unroll
        for (int o=16;o;o>>=1) l[j] += __shfl_xor_sync(0xffffffffu, l[j], o);
    float4 hv = *(const float4*)(hp + 128 + lane*4);
    float4 wv = *(const float4*)(vw2 + lane*4);
    float v = hv.x*wv.x + hv.y*wv.y + hv.z*wv.z + hv.w*wv.w;
    #pragma unroll
    for (int o=16;o;o>>=1) v += __shfl_xor_sync(0xffffffffu, v, o);
    if (lane == 0){
        float m = -1e30f;
        #pragma unroll
        for (int j=0;j<AD;j++){ l[j] += ab2[j]; m = fmaxf(m, l[j]); }
        float s = 0.f;
        #pragma unroll
        for (int j=0;j<AD;j++) s += expf(l[j]-m);
        float ls = logf(s) + m;
        #pragma unroll
        for (int j=0;j<AD;j++) out[(long)n*AD + j] = l[j] - ls;
        out[(long)NN*AD + n] = v + vb2[0];
    }
}

// ---------------- host ----------------
extern "C" void kernel_launch(void* const* d_in, const int* in_sizes, int n_in,
                              void* d_out, int out_size)
{
    const float* obs  = (const float*)d_in[0];
    const int*   ei   = (const int*)d_in[1];
    const int*   ga   = (const int*)d_in[2];
    const int*   cn   = (const int*)d_in[3];
    const float* embw = (const float*)d_in[4];  const float* embb = (const float*)d_in[5];
    const float* wl   = (const float*)d_in[6];  const float* wr   = (const float*)d_in[7];
    const float* att  = (const float*)d_in[8];  const float* gbias= (const float*)d_in[9];
    const float* ainw = (const float*)d_in[10]; const float* ainb = (const float*)d_in[11];
    const float* aow  = (const float*)d_in[12]; const float* aob  = (const float*)d_in[13];
    const float* ln1g = (const float*)d_in[14]; const float* ln1b = (const float*)d_in[15];
    const float* ln2g = (const float*)d_in[16]; const float* ln2b = (const float*)d_in[17];
    const float* fw1  = (const float*)d_in[18]; const float* fb1  = (const float*)d_in[19];
    const float* fw2  = (const float*)d_in[20]; const float* fb2  = (const float*)d_in[21];
    const float* aw1  = (const float*)d_in[22]; const float* ab1  = (const float*)d_in[23];
    const float* aw2  = (const float*)d_in[24]; const float* ab2  = (const float*)d_in[25];
    const float* vw1  = (const float*)d_in[26]; const float* vb1  = (const float*)d_in[27];
    const float* vw2  = (const float*)d_in[28]; const float* vb2  = (const float*)d_in[29];
    float* out = (float*)d_out;

    void *pv;
    cudaGetSymbolAddress(&pv, g_x);     float* fx    = (float*)pv;
    cudaGetSymbolAddress(&pv, g_xlr);   float* fxlr  = (float*)pv;
    cudaGetSymbolAddress(&pv, g_intra); float* fintra= (float*)pv;
    cudaGetSymbolAddress(&pv, g_hid);   float* fhid  = (float*)pv;
    cudaGetSymbolAddress(&pv, g_c);     float* fc    = (float*)pv;
    cudaGetSymbolAddress(&pv, g_qkv);   float* fqkv  = (float*)pv;
    cudaGetSymbolAddress(&pv, g_sc);    float* fsc   = (float*)pv;
    cudaGetSymbolAddress(&pv, g_o);     float* fo    = (float*)pv;
    cudaGetSymbolAddress(&pv, g_t1);    float* ft1   = (float*)pv;
    cudaGetSymbolAddress(&pv, g_h1);    float* fh1   = (float*)pv;
    cudaGetSymbolAddress(&pv, g_f);     float* ff    = (float*)pv;
    cudaGetSymbolAddress(&pv, g_gobs);  float* fgobs = (float*)pv;
    cudaGetSymbolAddress(&pv, g_pg);    float* fpg   = (float*)pv;

    const int GB = (NN + 127) / 128;   // 391 row blocks for N=50000

    // CSR build
    k_init <<<(NN+255)/256, 256>>>();
    k_count<<<(EE+255)/256, 256>>>(ei);
    k_scan <<<1, 1024>>>();

    // x = tanh(obs @ emb_w + b)          [50000,256]@[256,128]
    k_gemm128<1><<<dim3(GB,1),256>>>(obs, embw,nullptr, embb,nullptr, nullptr,nullptr,
                                     fx, NN, OBSD, OBSD, HD);
    // [xl|xr] = x @ [Wl|Wr]              [50000,128]@[128,128] x2 (grid.y selects Wl/Wr)
    k_gemm128<0><<<dim3(GB,2),256>>>(fx, wl,wr, nullptr,nullptr, nullptr,nullptr,
                                     fxlr, NN, HD, HD, 2*HD);
    // edge scores -> CSR, then segment softmax-aggregate
    k_edge<<<(ENE+7)/8, 256>>>(ei, att);
    k_agg <<<(NN+7)/8, 256>>>(gbias);

    // transformer over core nodes
    k_gather_c<<<(GD*HD+255)/256, 256>>>(cn);
    dim3 g3((GD+63)/64, (3*HD+63)/64);
    k_sgemm<0,0><<<g3,256>>>(fc, ainw,nullptr, ainb,nullptr,
                             fqkv, GD,3*HD,HD, HD,3*HD,1,3*HD, 0,0,0);
    // scores[h] = Q_h @ K_h^T   (grid.z = heads)
    dim3 g4((GD+63)/64, (GD+63)/64, 4);
    k_sgemm<0,0><<<g4,256>>>(fqkv, fqkv+HD,nullptr, nullptr,nullptr,
                             fsc, GD,GD,32, 3*HD,1,3*HD,GD, 32,32,(long)GD*GD);
    k_softmax<<<(4*GD+7)/8, 256>>>();
    // o[h] = attn_h @ V_h
    dim3 g5((GD+63)/64, 1, 4);
    k_sgemm<0,0><<<g5,256>>>(fsc, fqkv+2*HD,nullptr, nullptr,nullptr,
                             fo, GD,32,GD, GD,3*HD,1,HD, (long)GD*GD,32,32);
    // out-proj, LN1, FFN, LN2+tanh
    dim3 g6((GD+63)/64, (HD+63)/64);
    k_sgemm<0,0><<<g6,256>>>(fo, aow,nullptr, aob,nullptr,
                             ft1, GD,HD,HD, HD,HD,1,HD, 0,0,0);
    k_ln<0><<<(GD+7)/8, 256>>>(fc, ft1, ln1g, ln1b, fh1, GD);
    k_sgemm<0,2><<<g6,256>>>(fh1, fw1,nullptr, fb1,nullptr,
                             ff, GD,HD,HD, HD,HD,1,HD, 0,0,0);
    k_sgemm<0,0><<<g6,256>>>(ff, fw2,nullptr, fb2,nullptr,
                             ft1, GD,HD,HD, HD,HD,1,HD, 0,0,0);
    k_ln<1><<<(GD+7)/8, 256>>>(fh1, ft1, ln2g, ln2b, fgobs, GD);

    // PG = gobs @ [actor_w1_top | value_w1_top]   [1024,128]@[128,256] (tiny)
    dim3 g8((GD+63)/64, (2*HD+63)/64);
    k_sgemm<1,0><<<g8,256>>>(fgobs, aw1,vw1, nullptr,nullptr,
                             fpg, GD,2*HD,HD, HD,0,0,2*HD, 0,0,0);
    // hidden = tanh( intra @ [actor_w1_bot | value_w1_bot] + bias + PG[ga] )
    k_gemm128<3><<<dim3(GB,2),256>>>(fintra, aw1 + HD*HD, vw1 + HD*HD, ab1, vb1,
                                     fpg, ga, fhid, NN, HD, HD, 2*HD);
    // final logits + log_softmax + value
    k_heads<<<(NN+7)/8, 256>>>(aw2, ab2, vw2, vb2, out);
}

// round 9
// speedup vs baseline: 1.5951x; 1.1071x over previous
#include <cuda_runtime.h>
#include <math.h>

#define NN   50000
#define EE   800000
#define ENE  (NN+EE)
#define OBSD 256
#define HD   128
#define GD   1024
#define AD   10

// ---------------- scratch (static device globals; no allocation) ----------------
__device__ __align__(16) float g_x[NN*HD];          // tanh embedding
__device__ __align__(16) float g_xlr[NN*2*HD];      // [xl | xr] per node
__device__ __align__(16) float g_intra[NN*HD];
__device__ __align__(16) float g_hid[NN*2*HD];      // [actor_hidden | value_hidden]
__device__ __align__(16) int   g_srcs[ENE];         // CSR-ordered edge sources
__device__ int   g_cnt[NN];
__device__ int   g_cur[NN];
__device__ int   g_off[NN+1];
__device__ __align__(16) float g_c[GD*HD];
__device__ __align__(16) float g_qkv[GD*3*HD];
__device__ __align__(16) float g_sc[4*GD*GD];
__device__ __align__(16) float g_o[GD*HD];
__device__ __align__(16) float g_t1[GD*HD];
__device__ __align__(16) float g_h1[GD*HD];
__device__ __align__(16) float g_f[GD*HD];
__device__ __align__(16) float g_gobs[GD*HD];
__device__ __align__(16) float g_pg[GD*2*HD];       // gobs @ [actor_w1_top | value_w1_top]

__device__ __forceinline__ float lrelu(float x){ return x > 0.f ? x : 0.2f*x; }

// ================= big-tile SGEMM: 128x128 block, 8x8/thread, reg-prefetch =================
// C[row, bn+col] = epi( A[row,:K] @ B[:,col] + bias[col] (+ PG[gidx[row]*256+bn+col]) )
// B selected per blockIdx.y (column block of 128): y==0 -> B0/bias0, y==1 -> B1/bias1.
// B layout: B[k*128 + col], fixed ldb=128. EPI: 0 none, 1 tanh, 3 tanh + PG gather add.
template<int EPI>
__global__ __launch_bounds__(256) void k_gemm128(
    const float* __restrict__ A,
    const float* __restrict__ B0, const float* __restrict__ B1,
    const float* __restrict__ bias0, const float* __restrict__ bias1,
    const float* __restrict__ PG, const int* __restrict__ gidx,
    float* __restrict__ C,
    int M, int K, int lda, int ldc)
{
    __shared__ float As[16][132];
    __shared__ float Bs[16][128];
    const float* B    = blockIdx.y ? B1 : B0;
    const float* bias = blockIdx.y ? bias1 : bias0;
    const int bn = blockIdx.y * 128;
    const int bm = blockIdx.x * 128;
    const int tid = threadIdx.x;
    const int tx = tid & 15, ty = tid >> 4;

    const int arow = tid >> 1;
    const int akk  = (tid & 1) * 8;
    const int grow = bm + arow;
    const bool rok = (grow < M);
    const float* Ap = A + (long)grow * lda;

    const int bkk  = tid >> 5;
    const int bcol = (tid & 31) * 4;

    float acc[8][8];
    #pragma unroll
    for (int i=0;i<8;i++)
        #pragma unroll
        for (int j=0;j<8;j++) acc[i][j] = 0.f;

    // prologue: load first tile into registers
    float4 av0 = make_float4(0,0,0,0), av1 = make_float4(0,0,0,0);
    if (rok){
        av0 = *(const float4*)(Ap + akk);
        av1 = *(const float4*)(Ap + akk + 4);
    }
    float4 bv0 = *(const float4*)(B + (long)(bkk  )*128 + bcol);
    float4 bv1 = *(const float4*)(B + (long)(bkk+8)*128 + bcol);

    for (int k0=0; k0<K; k0+=16){
        As[akk+0][arow]=av0.x; As[akk+1][arow]=av0.y; As[akk+2][arow]=av0.z; As[akk+3][arow]=av0.w;
        As[akk+4][arow]=av1.x; As[akk+5][arow]=av1.y; As[akk+6][arow]=av1.z; As[akk+7][arow]=av1.w;
        *(float4*)&Bs[bkk  ][bcol] = bv0;
        *(float4*)&Bs[bkk+8][bcol] = bv1;
        __syncthreads();
        // prefetch next tile (overlaps with compute below)
        float4 na0 = make_float4(0,0,0,0), na1 = make_float4(0,0,0,0);
        float4 nb0 = make_float4(0,0,0,0), nb1 = make_float4(0,0,0,0);
        if (k0 + 16 < K){
            if (rok){
                na0 = *(const float4*)(Ap + k0 + 16 + akk);
                na1 = *(const float4*)(Ap + k0 + 16 + akk + 4);
            }
            nb0 = *(const float4*)(B + (long)(k0+16+bkk  )*128 + bcol);
            nb1 = *(const float4*)(B + (long)(k0+16+bkk+8)*128 + bcol);
        }
        #pragma unroll
        for (int kk=0; kk<16; kk++){
            float4 a0 = *(const float4*)&As[kk][ty*4];
            float4 a1 = *(const float4*)&As[kk][64 + ty*4];
            float4 b0 = *(const float4*)&Bs[kk][tx*4];
            float4 b1 = *(const float4*)&Bs[kk][64 + tx*4];
            float ar[8] = {a0.x,a0.y,a0.z,a0.w,a1.x,a1.y,a1.z,a1.w};
            float br[8] = {b0.x,b0.y,b0.z,b0.w,b1.x,b1.y,b1.z,b1.w};
            #pragma unroll
            for (int i=0;i<8;i++)
                #pragma unroll
                for (int j=0;j<8;j++) acc[i][j] += ar[i]*br[j];
        }
        __syncthreads();
        av0 = na0; av1 = na1; bv0 = nb0; bv1 = nb1;
    }

    #pragma unroll
    for (int i=0;i<8;i++){
        int r = bm + ((i<4) ? (ty*4+i) : (64 + ty*4 + i - 4));
        if (r >= M) continue;
        int gi = 0;
        if (EPI==3) gi = gidx[r];
        #pragma unroll
        for (int j=0;j<8;j++){
            int cl = (j<4) ? (tx*4+j) : (64 + tx*4 + j - 4);
            float v = acc[i][j];
            if (bias) v += bias[cl];
            if (EPI==3) v += PG[(long)gi*256 + bn + cl];
            if (EPI==1 || EPI==3) v = tanhf(v);
            C[(long)r*ldc + bn + cl] = v;
        }
    }
}

// ---------------- generic tiled SGEMM (64x64), kept for small/odd shapes ----------------
template<int BMODE,int ACT>
__global__ __launch_bounds__(256) void k_sgemm(
    const float* __restrict__ A,
    const float* __restrict__ B, const float* __restrict__ B2,
    const float* __restrict__ bias, const float* __restrict__ bias2,
    float* __restrict__ C,
    int M, int N, int K, int lda, int ldbk, int ldbn, int ldc,
    long zA, long zB, long zC)
{
    const int BM=64, BN=64, BK=16;
    __shared__ float As[BK][BM+4];
    __shared__ float Bs[BK][BN+4];
    A += (long)blockIdx.z * zA;
    B += (long)blockIdx.z * zB;
    C += (long)blockIdx.z * zC;
    int bm = blockIdx.x*BM, bn = blockIdx.y*BN;
    int tid = threadIdx.x;
    int tx = tid & 15, ty = tid >> 4;
    float acc[4][4];
    #pragma unroll
    for (int i=0;i<4;i++)
        #pragma unroll
        for (int j=0;j<4;j++) acc[i][j]=0.f;

    for (int k0=0;k0<K;k0+=BK){
        #pragma unroll
        for (int t=0;t<4;t++){
            int i = tid + t*256;
            int m = i >> 4, kk = i & 15;
            int row = bm + m, k = k0 + kk;
            float v = 0.f;
            if (row < M && k < K) v = A[(long)row*lda + k];
            As[kk][m] = v;
            int kk2 = i >> 6, n = i & 63;
            int col = bn + n, k2 = k0 + kk2;
            float w = 0.f;
            if (col < N && k2 < K){
                if (BMODE==0) w = B[(long)k2*ldbk + (long)col*ldbn];
                else          w = (col < HD) ? B[(long)k2*HD + col]
                                             : B2[(long)k2*HD + (col-HD)];
            }
            Bs[kk2][n] = w;
        }
        __syncthreads();
        #pragma unroll
        for (int kk=0;kk<BK;kk++){
            float a0=As[kk][ty*4+0], a1=As[kk][ty*4+1], a2=As[kk][ty*4+2], a3=As[kk][ty*4+3];
            float b0=Bs[kk][tx*4+0], b1=Bs[kk][tx*4+1], b2=Bs[kk][tx*4+2], b3=Bs[kk][tx*4+3];
            acc[0][0]+=a0*b0; acc[0][1]+=a0*b1; acc[0][2]+=a0*b2; acc[0][3]+=a0*b3;
            acc[1][0]+=a1*b0; acc[1][1]+=a1*b1; acc[1][2]+=a1*b2; acc[1][3]+=a1*b3;
            acc[2][0]+=a2*b0; acc[2][1]+=a2*b1; acc[2][2]+=a2*b2; acc[2][3]+=a2*b3;
            acc[3][0]+=a3*b0; acc[3][1]+=a3*b1; acc[3][2]+=a3*b2; acc[3][3]+=a3*b3;
        }
        __syncthreads();
    }
    #pragma unroll
    for (int i=0;i<4;i++){
        int row = bm + ty*4 + i;
        if (row >= M) continue;
        #pragma unroll
        for (int j=0;j<4;j++){
            int col = bn + tx*4 + j;
            if (col >= N) continue;
            float v = acc[i][j];
            if (BMODE==1){ if (bias) v += (col < HD) ? bias[col] : bias2[col-HD]; }
            else if (bias)           v += bias[col];
            if (ACT==1) v = tanhf(v);
            if (ACT==2) v = fmaxf(v, 0.f);
            C[(long)row*ldc + col] = v;
        }
    }
}

// ---------------- GAT pipeline: CSR build + fused online-softmax aggregation ----------------
__global__ void k_init(){
    int i = blockIdx.x*blockDim.x + threadIdx.x;
    if (i < NN){ g_cnt[i] = 1; g_cur[i] = 0; }   // 1 = self loop
    if (i == 0) g_off[NN] = ENE;
}

__global__ void k_count(const int* __restrict__ ei){
    int i = blockIdx.x*blockDim.x + threadIdx.x;
    if (i < EE) atomicAdd(&g_cnt[ei[EE+i]], 1);
}

__global__ void k_scan(){
    __shared__ int sh[1024];
    int t = threadIdx.x;
    const int chunk = (NN + 1023) / 1024;   // 49
    int base = t * chunk;
    int s = 0;
    for (int i=0;i<chunk;i++){ int idx = base+i; if (idx < NN) s += g_cnt[idx]; }
    sh[t] = s; __syncthreads();
    for (int d=1; d<1024; d<<=1){
        int v = (t >= d) ? sh[t-d] : 0;
        __syncthreads();
        sh[t] += v;
        __syncthreads();
    }
    int run = sh[t] - s;   // exclusive prefix
    for (int i=0;i<chunk;i++){
        int idx = base+i;
        if (idx < NN){ g_off[idx] = run; run += g_cnt[idx]; }
    }
}

// scatter src ids into CSR slots (scores computed later, fused into aggregation)
__global__ void k_scatter(const int* __restrict__ ei){
    int i = blockIdx.x*blockDim.x + threadIdx.x;
    if (i >= ENE) return;
    int src, dst;
    if (i < EE){ src = ei[i]; dst = ei[EE+i]; } else { src = dst = i - EE; }
    int pos = g_off[dst] + atomicAdd(&g_cur[dst], 1);
    g_srcs[pos] = src;
}

// warp per dst node: single pass over incident edges with ONLINE softmax.
// Each xl[src] row is loaded exactly once and used for both the attention
// score and the weighted aggregate (flash-attention-style m/s/acc rescaling).
__global__ void k_aggf(const float* __restrict__ att, const float* __restrict__ gbias){
    int n = blockIdx.x*(blockDim.x>>5) + (threadIdx.x>>5);
    if (n >= NN) return;
    int lane = threadIdx.x & 31;
    float4 xr = *(const float4*)(g_xlr + (long)n*256 + 128 + lane*4);
    float4 at = *(const float4*)(att + lane*4);
    int s0 = g_off[n], s1 = g_off[n+1];
    float m = -1e30f, s = 0.f;
    float4 acc = make_float4(0.f,0.f,0.f,0.f);
    for (int j=s0; j<s1; j++){
        int sr = g_srcs[j];                                    // warp-broadcast load
        float4 xv = *(const float4*)(g_xlr + (long)sr*256 + lane*4);
        float e = lrelu(xv.x+xr.x)*at.x + lrelu(xv.y+xr.y)*at.y
                + lrelu(xv.z+xr.z)*at.z + lrelu(xv.w+xr.w)*at.w;
        #pragma unroll
        for (int o=16;o;o>>=1) e += __shfl_xor_sync(0xffffffffu, e, o);
        float mn = fmaxf(m, e);
        float sc = expf(m - mn);        // first iter: exp(-inf) = 0
        float w  = expf(e - mn);
        s = s*sc + w;
        acc.x = acc.x*sc + w*xv.x;
        acc.y = acc.y*sc + w*xv.y;
        acc.z = acc.z*sc + w*xv.z;
        acc.w = acc.w*sc + w*xv.w;
        m = mn;
    }
    float inv = 1.f / s;
    float4 bv = *(const float4*)(gbias + lane*4);
    float* op = g_intra + (long)n*HD + lane*4;
    op[0] = tanhf(acc.x*inv + bv.x);
    op[1] = tanhf(acc.y*inv + bv.y);
    op[2] = tanhf(acc.z*inv + bv.z);
    op[3] = tanhf(acc.w*inv + bv.w);
}

// ---------------- transformer helpers ----------------
__global__ void k_gather_c(const int* __restrict__ cn){
    int i = blockIdx.x*blockDim.x + threadIdx.x;
    if (i < GD*HD) g_c[i] = g_intra[(long)cn[i>>7]*HD + (i & 127)];
}

__global__ void k_softmax(){
    int r = blockIdx.x*(blockDim.x>>5) + (threadIdx.x>>5);
    if (r >= 4*GD) return;
    int lane = threadIdx.x & 31;
    float* p = g_sc + (long)r*GD;
    const float scale = 0.17677669529663687f;   // 1/sqrt(32)
    float v[32];
    float m = -1e30f;
    #pragma unroll
    for (int i=0;i<32;i++){ v[i] = p[lane + 32*i] * scale; m = fmaxf(m, v[i]); }
    #pragma unroll
    for (int o=16;o;o>>=1) m = fmaxf(m, __shfl_xor_sync(0xffffffffu, m, o));
    float s = 0.f;
    #pragma unroll
    for (int i=0;i<32;i++){ v[i] = expf(v[i]-m); s += v[i]; }
    #pragma unroll
    for (int o=16;o;o>>=1) s += __shfl_xor_sync(0xffffffffu, s, o);
    float inv = 1.f / s;
    #pragma unroll
    for (int i=0;i<32;i++) p[lane + 32*i] = v[i]*inv;
}

// out = [tanh]( LN(x + y) * g + b ), warp per row of 128
template<int TANH>
__global__ void k_ln(const float* __restrict__ x, const float* __restrict__ y,
                     const float* __restrict__ g, const float* __restrict__ b,
                     float* __restrict__ out, int rows){
    int r = blockIdx.x*(blockDim.x>>5) + (threadIdx.x>>5);
    if (r >= rows) return;
    int lane = threadIdx.x & 31;
    float4 xv = *(const float4*)(x + (long)r*HD + lane*4);
    float4 yv = *(const float4*)(y + (long)r*HD + lane*4);
    float v0 = xv.x+yv.x, v1 = xv.y+yv.y, v2 = xv.z+yv.z, v3 = xv.w+yv.w;
    float s = v0+v1+v2+v3;
    #pragma unroll
    for (int o=16;o;o>>=1) s += __shfl_xor_sync(0xffffffffu, s, o);
    float mu = s * (1.f/128.f);
    float d0=v0-mu, d1=v1-mu, d2=v2-mu, d3=v3-mu;
    float q = d0*d0 + d1*d1 + d2*d2 + d3*d3;
    #pragma unroll
    for (int o=16;o;o>>=1) q += __shfl_xor_sync(0xffffffffu, q, o);
    float rs = rsqrtf(q * (1.f/128.f) + 1e-5f);
    float4 gv = *(const float4*)(g + lane*4);
    float4 bv = *(const float4*)(b + lane*4);
    float o0 = d0*rs*gv.x + bv.x;
    float o1 = d1*rs*gv.y + bv.y;
    float o2 = d2*rs*gv.z + bv.z;
    float o3 = d3*rs*gv.w + bv.w;
    if (TANH){ o0=tanhf(o0); o1=tanhf(o1); o2=tanhf(o2); o3=tanhf(o3); }
    *(float4*)(out + (long)r*HD + lane*4) = make_float4(o0,o1,o2,o3);
}

// ---------------- final heads: warp per node ----------------
__global__ void k_heads(const float* __restrict__ aw2, const float* __restrict__ ab2,
                        const float* __restrict__ vw2, const float* __restrict__ vb2,
                        float* __restrict__ out){
    int n = blockIdx.x*(blockDim.x>>5) + (threadIdx.x>>5);
    if (n >= NN) return;
    int lane = threadIdx.x & 31;
    const float* hp = g_hid + (long)n*256;
    float4 ha = *(const float4*)(hp + lane*4);
    float l[AD];
    #pragma unroll
    for (int j=0;j<AD;j++){
        l[j] = ha.x*aw2[(lane*4+0)*AD+j] + ha.y*aw2[(lane*4+1)*AD+j]
             + ha.z*aw2[(lane*4+2)*AD+j] + ha.w*aw2[(lane*4+3)*AD+j];
    }
    #pragma unroll
    for (int j=0;j<AD;j++)
        #pragma unroll
        for (int o=16;o;o>>=1) l[j] += __shfl_xor_sync(0xffffffffu, l[j], o);
    float4 hv = *(const float4*)(hp + 128 + lane*4);
    float4 wv = *(const float4*)(vw2 + lane*4);
    float v = hv.x*wv.x + hv.y*wv.y + hv.z*wv.z + hv.w*wv.w;
    #pragma unroll
    for (int o=16;o;o>>=1) v += __shfl_xor_sync(0xffffffffu, v, o);
    if (lane == 0){
        float m = -1e30f;
        #pragma unroll
        for (int j=0;j<AD;j++){ l[j] += ab2[j]; m = fmaxf(m, l[j]); }
        float s = 0.f;
        #pragma unroll
        for (int j=0;j<AD;j++) s += expf(l[j]-m);
        float ls = logf(s) + m;
        #pragma unroll
        for (int j=0;j<AD;j++) out[(long)n*AD + j] = l[j] - ls;
        out[(long)NN*AD + n] = v + vb2[0];
    }
}

// ---------------- host ----------------
extern "C" void kernel_launch(void* const* d_in, const int* in_sizes, int n_in,
                              void* d_out, int out_size)
{
    const float* obs  = (const float*)d_in[0];
    const int*   ei   = (const int*)d_in[1];
    const int*   ga   = (const int*)d_in[2];
    const int*   cn   = (const int*)d_in[3];
    const float* embw = (const float*)d_in[4];  const float* embb = (const float*)d_in[5];
    const float* wl   = (const float*)d_in[6];  const float* wr   = (const float*)d_in[7];
    const float* att  = (const float*)d_in[8];  const float* gbias= (const float*)d_in[9];
    const float* ainw = (const float*)d_in[10]; const float* ainb = (const float*)d_in[11];
    const float* aow  = (const float*)d_in[12]; const float* aob  = (const float*)d_in[13];
    const float* ln1g = (const float*)d_in[14]; const float* ln1b = (const float*)d_in[15];
    const float* ln2g = (const float*)d_in[16]; const float* ln2b = (const float*)d_in[17];
    const float* fw1  = (const float*)d_in[18]; const float* fb1  = (const float*)d_in[19];
    const float* fw2  = (const float*)d_in[20]; const float* fb2  = (const float*)d_in[21];
    const float* aw1  = (const float*)d_in[22]; const float* ab1  = (const float*)d_in[23];
    const float* aw2  = (const float*)d_in[24]; const float* ab2  = (const float*)d_in[25];
    const float* vw1  = (const float*)d_in[26]; const float* vb1  = (const float*)d_in[27];
    const float* vw2  = (const float*)d_in[28]; const float* vb2  = (const float*)d_in[29];
    float* out = (float*)d_out;

    void *pv;
    cudaGetSymbolAddress(&pv, g_x);     float* fx    = (float*)pv;
    cudaGetSymbolAddress(&pv, g_xlr);   float* fxlr  = (float*)pv;
    cudaGetSymbolAddress(&pv, g_intra); float* fintra= (float*)pv;
    cudaGetSymbolAddress(&pv, g_hid);   float* fhid  = (float*)pv;
    cudaGetSymbolAddress(&pv, g_c);     float* fc    = (float*)pv;
    cudaGetSymbolAddress(&pv, g_qkv);   float* fqkv  = (float*)pv;
    cudaGetSymbolAddress(&pv, g_sc);    float* fsc   = (float*)pv;
    cudaGetSymbolAddress(&pv, g_o);     float* fo    = (float*)pv;
    cudaGetSymbolAddress(&pv, g_t1);    float* ft1   = (float*)pv;
    cudaGetSymbolAddress(&pv, g_h1);    float* fh1   = (float*)pv;
    cudaGetSymbolAddress(&pv, g_f);     float* ff    = (float*)pv;
    cudaGetSymbolAddress(&pv, g_gobs);  float* fgobs = (float*)pv;
    cudaGetSymbolAddress(&pv, g_pg);    float* fpg   = (float*)pv;

    const int GB = (NN + 127) / 128;   // 391 row blocks for N=50000

    // CSR build (src ids only; scores fused into k_aggf)
    k_init   <<<(NN+255)/256, 256>>>();
    k_count  <<<(EE+255)/256, 256>>>(ei);
    k_scan   <<<1, 1024>>>();
    k_scatter<<<(ENE+255)/256, 256>>>(ei);

    // x = tanh(obs @ emb_w + b)          [50000,256]@[256,128]
    k_gemm128<1><<<dim3(GB,1),256>>>(obs, embw,nullptr, embb,nullptr, nullptr,nullptr,
                                     fx, NN, OBSD, OBSD, HD);
    // [xl|xr] = x @ [Wl|Wr]              [50000,128]@[128,128] x2 (grid.y selects Wl/Wr)
    k_gemm128<0><<<dim3(GB,2),256>>>(fx, wl,wr, nullptr,nullptr, nullptr,nullptr,
                                     fxlr, NN, HD, HD, 2*HD);
    // fused GAT: online-softmax attention + aggregation, one xl load per edge
    k_aggf<<<(NN+7)/8, 256>>>(att, gbias);

    // transformer over core nodes
    k_gather_c<<<(GD*HD+255)/256, 256>>>(cn);
    dim3 g3((GD+63)/64, (3*HD+63)/64);
    k_sgemm<0,0><<<g3,256>>>(fc, ainw,nullptr, ainb,nullptr,
                             fqkv, GD,3*HD,HD, HD,3*HD,1,3*HD, 0,0,0);
    // scores[h] = Q_h @ K_h^T   (grid.z = heads)
    dim3 g4((GD+63)/64, (GD+63)/64, 4);
    k_sgemm<0,0><<<g4,256>>>(fqkv, fqkv+HD,nullptr, nullptr,nullptr,
                             fsc, GD,GD,32, 3*HD,1,3*HD,GD, 32,32,(long)GD*GD);
    k_softmax<<<(4*GD+7)/8, 256>>>();
    // o[h] = attn_h @ V_h
    dim3 g5((GD+63)/64, 1, 4);
    k_sgemm<0,0><<<g5,256>>>(fsc, fqkv+2*HD,nullptr, nullptr,nullptr,
                             fo, GD,32,GD, GD,3*HD,1,HD, (long)GD*GD,32,32);
    // out-proj, LN1, FFN, LN2+tanh
    dim3 g6((GD+63)/64, (HD+63)/64);
    k_sgemm<0,0><<<g6,256>>>(fo, aow,nullptr, aob,nullptr,
                             ft1, GD,HD,HD, HD,HD,1,HD, 0,0,0);
    k_ln<0><<<(GD+7)/8, 256>>>(fc, ft1, ln1g, ln1b, fh1, GD);
    k_sgemm<0,2><<<g6,256>>>(fh1, fw1,nullptr, fb1,nullptr,
                             ff, GD,HD,HD, HD,HD,1,HD, 0,0,0);
    k_sgemm<0,0><<<g6,256>>>(ff, fw2,nullptr, fb2,nullptr,
                             ft1, GD,HD,HD, HD,HD,1,HD, 0,0,0);
    k_ln<1><<<(GD+7)/8, 256>>>(fh1, ft1, ln2g, ln2b, fgobs, GD);

    // PG = gobs @ [actor_w1_top | value_w1_top]   [1024,128]@[128,256] (tiny)
    dim3 g8((GD+63)/64, (2*HD+63)/64);
    k_sgemm<1,0><<<g8,256>>>(fgobs, aw1,vw1, nullptr,nullptr,
                             fpg, GD,2*HD,HD, HD,0,0,2*HD, 0,0,0);
    // hidden = tanh( intra @ [actor_w1_bot | value_w1_bot] + bias + PG[ga] )
    k_gemm128<3><<<dim3(GB,2),256>>>(fintra, aw1 + HD*HD, vw1 + HD*HD, ab1, vb1,
                                     fpg, ga, fhid, NN, HD, HD, 2*HD);
    // final logits + log_softmax + value
    k_heads<<<(NN+7)/8, 256>>>(aw2, ab2, vw2, vb2, out);
}

// round 10
// speedup vs baseline: 1.9352x; 1.2132x over previous
#include <cuda_runtime.h>
#include <math.h>

#define NN   50000
#define EE   800000
#define ENE  (NN+EE)
#define OBSD 256
#define HD   128
#define GD   1024
#define AD   10

// ---------------- scratch (static device globals; no allocation) ----------------
__device__ __align__(16) float g_x[NN*HD];          // tanh embedding
__device__ __align__(16) float g_xlr[NN*2*HD];      // [xl | xr] per node
__device__ __align__(16) float g_intra[NN*HD];
__device__ __align__(16) float g_hid[NN*2*HD];      // [actor_hidden | value_hidden]
__device__ __align__(16) int   g_srcs[ENE];         // CSR-ordered edge sources
__device__ int   g_cnt[NN];
__device__ int   g_cur[NN];
__device__ int   g_off[NN+1];
__device__ __align__(16) float g_c[GD*HD];
__device__ __align__(16) float g_qkv[GD*3*HD];
__device__ __align__(16) float g_sc[4*GD*GD];
__device__ __align__(16) float g_o[GD*HD];
__device__ __align__(16) float g_t1[GD*HD];
__device__ __align__(16) float g_h1[GD*HD];
__device__ __align__(16) float g_f[GD*HD];
__device__ __align__(16) float g_gobs[GD*HD];
__device__ __align__(16) float g_pg[GD*2*HD];       // gobs @ [actor_w1_top | value_w1_top]

__device__ __forceinline__ float lrelu(float x){ return x > 0.f ? x : 0.2f*x; }

__device__ __forceinline__ unsigned f2tf(float x){
    unsigned u; asm("cvt.rna.tf32.f32 %0, %1;" : "=r"(u) : "f"(x)); return u;
}

__device__ __forceinline__ void mma_tf32(float* d, const unsigned* a, const unsigned* b){
    asm volatile("mma.sync.aligned.m16n8k8.row.col.f32.tf32.tf32.f32 "
        "{%0,%1,%2,%3}, {%4,%5,%6,%7}, {%8,%9}, {%0,%1,%2,%3};"
        : "+f"(d[0]), "+f"(d[1]), "+f"(d[2]), "+f"(d[3])
        : "r"(a[0]), "r"(a[1]), "r"(a[2]), "r"(a[3]), "r"(b[0]), "r"(b[1]));
}

// ============ tf32 tensor-core GEMM: 128x128 CTA tile, 8 warps (2x4), 64x32/warp ============
// C[row, bn+col] = epi( A[row,:K] @ B[:,col] + bias[col] (+ PG[gidx[row]*256+bn+col]) )
// B selected per blockIdx.y: y==0 -> B0/bias0, y==1 -> B1/bias1.  B layout B[k*128+col].
// EPI: 0 none, 1 tanh, 3 tanh + PG gather add.   K must be a multiple of 16.
template<int EPI>
__global__ __launch_bounds__(256) void k_tgemm(
    const float* __restrict__ A,
    const float* __restrict__ B0, const float* __restrict__ B1,
    const float* __restrict__ bias0, const float* __restrict__ bias1,
    const float* __restrict__ PG, const int* __restrict__ gidx,
    float* __restrict__ C,
    int M, int K, int lda, int ldc)
{
    __shared__ unsigned As[16][136];   // [k][row], pad 136 -> fragment LDS conflict-free
    __shared__ unsigned Bs[16][136];   // [k][col]
    const float* B    = blockIdx.y ? B1 : B0;
    const float* bias = blockIdx.y ? bias1 : bias0;
    const int bn = blockIdx.y * 128;
    const int bm = blockIdx.x * 128;
    const int tid = threadIdx.x;

    // global->smem assignments (same as fp32 version)
    const int arow = tid >> 1;
    const int akk  = (tid & 1) * 8;
    const int grow = bm + arow;
    const bool rok = (grow < M);
    const float* Ap = A + (long)grow * lda;
    const int bkk  = tid >> 5;
    const int bcol = (tid & 31) * 4;

    // mma lane decomposition
    const int lane = tid & 31;
    const int gid  = lane >> 2;        // 0..7
    const int tig  = lane & 3;         // 0..3
    const int w    = tid >> 5;         // warp 0..7
    const int wm   = (w >> 2) * 64;    // warp row offset in tile
    const int wn   = (w & 3) * 32;     // warp col offset in tile

    float d[4][4][4];
    #pragma unroll
    for (int mi=0;mi<4;mi++)
        #pragma unroll
        for (int nj=0;nj<4;nj++)
            #pragma unroll
            for (int q=0;q<4;q++) d[mi][nj][q] = 0.f;

    // prologue: first tile into registers
    float4 av0 = make_float4(0,0,0,0), av1 = make_float4(0,0,0,0);
    if (rok){
        av0 = *(const float4*)(Ap + akk);
        av1 = *(const float4*)(Ap + akk + 4);
    }
    float4 bv0 = *(const float4*)(B + (long)(bkk  )*128 + bcol);
    float4 bv1 = *(const float4*)(B + (long)(bkk+8)*128 + bcol);

    for (int k0=0; k0<K; k0+=16){
        As[akk+0][arow]=f2tf(av0.x); As[akk+1][arow]=f2tf(av0.y);
        As[akk+2][arow]=f2tf(av0.z); As[akk+3][arow]=f2tf(av0.w);
        As[akk+4][arow]=f2tf(av1.x); As[akk+5][arow]=f2tf(av1.y);
        As[akk+6][arow]=f2tf(av1.z); As[akk+7][arow]=f2tf(av1.w);
        Bs[bkk  ][bcol+0]=f2tf(bv0.x); Bs[bkk  ][bcol+1]=f2tf(bv0.y);
        Bs[bkk  ][bcol+2]=f2tf(bv0.z); Bs[bkk  ][bcol+3]=f2tf(bv0.w);
        Bs[bkk+8][bcol+0]=f2tf(bv1.x); Bs[bkk+8][bcol+1]=f2tf(bv1.y);
        Bs[bkk+8][bcol+2]=f2tf(bv1.z); Bs[bkk+8][bcol+3]=f2tf(bv1.w);
        __syncthreads();
        // prefetch next tile (overlaps with mma below)
        float4 na0 = make_float4(0,0,0,0), na1 = make_float4(0,0,0,0);
        float4 nb0 = make_float4(0,0,0,0), nb1 = make_float4(0,0,0,0);
        if (k0 + 16 < K){
            if (rok){
                na0 = *(const float4*)(Ap + k0 + 16 + akk);
                na1 = *(const float4*)(Ap + k0 + 16 + akk + 4);
            }
            nb0 = *(const float4*)(B + (long)(k0+16+bkk  )*128 + bcol);
            nb1 = *(const float4*)(B + (long)(k0+16+bkk+8)*128 + bcol);
        }
        #pragma unroll
        for (int k8=0; k8<16; k8+=8){
            unsigned af[4][4], bf[4][2];
            #pragma unroll
            for (int mi=0;mi<4;mi++){
                int r0 = wm + 16*mi + gid;
                af[mi][0] = As[k8+tig  ][r0];
                af[mi][1] = As[k8+tig  ][r0+8];
                af[mi][2] = As[k8+tig+4][r0];
                af[mi][3] = As[k8+tig+4][r0+8];
            }
            #pragma unroll
            for (int nj=0;nj<4;nj++){
                int c0 = wn + 8*nj + gid;
                bf[nj][0] = Bs[k8+tig  ][c0];
                bf[nj][1] = Bs[k8+tig+4][c0];
            }
            #pragma unroll
            for (int mi=0;mi<4;mi++)
                #pragma unroll
                for (int nj=0;nj<4;nj++)
                    mma_tf32(d[mi][nj], af[mi], bf[nj]);
        }
        __syncthreads();
        av0 = na0; av1 = na1; bv0 = nb0; bv1 = nb1;
    }

    // epilogue: each frag lane holds (r0,c),(r0,c+1),(r0+8,c),(r0+8,c+1)
    #pragma unroll
    for (int mi=0;mi<4;mi++){
        int r0 = bm + wm + 16*mi + gid;
        int r1 = r0 + 8;
        int gi0 = 0, gi1 = 0;
        if (EPI==3){
            if (r0 < M) gi0 = gidx[r0];
            if (r1 < M) gi1 = gidx[r1];
        }
        #pragma unroll
        for (int nj=0;nj<4;nj++){
            int lc = wn + 8*nj + 2*tig;
            float b0v = bias ? bias[lc]   : 0.f;
            float b1v = bias ? bias[lc+1] : 0.f;
            if (r0 < M){
                float v0 = d[mi][nj][0] + b0v;
                float v1 = d[mi][nj][1] + b1v;
                if (EPI==3){
                    v0 += PG[(long)gi0*256 + bn + lc];
                    v1 += PG[(long)gi0*256 + bn + lc + 1];
                }
                if (EPI==1 || EPI==3){ v0 = tanhf(v0); v1 = tanhf(v1); }
                *(float2*)(C + (long)r0*ldc + bn + lc) = make_float2(v0, v1);
            }
            if (r1 < M){
                float v2 = d[mi][nj][2] + b0v;
                float v3 = d[mi][nj][3] + b1v;
                if (EPI==3){
                    v2 += PG[(long)gi1*256 + bn + lc];
                    v3 += PG[(long)gi1*256 + bn + lc + 1];
                }
                if (EPI==1 || EPI==3){ v2 = tanhf(v2); v3 = tanhf(v3); }
                *(float2*)(C + (long)r1*ldc + bn + lc) = make_float2(v2, v3);
            }
        }
    }
}

// ---------------- generic tiled SGEMM (64x64), kept for small/odd shapes ----------------
template<int BMODE,int ACT>
__global__ __launch_bounds__(256) void k_sgemm(
    const float* __restrict__ A,
    const float* __restrict__ B, const float* __restrict__ B2,
    const float* __restrict__ bias, const float* __restrict__ bias2,
    float* __restrict__ C,
    int M, int N, int K, int lda, int ldbk, int ldbn, int ldc,
    long zA, long zB, long zC)
{
    const int BM=64, BN=64, BK=16;
    __shared__ float As[BK][BM+4];
    __shared__ float Bs[BK][BN+4];
    A += (long)blockIdx.z * zA;
    B += (long)blockIdx.z * zB;
    C += (long)blockIdx.z * zC;
    int bm = blockIdx.x*BM, bn = blockIdx.y*BN;
    int tid = threadIdx.x;
    int tx = tid & 15, ty = tid >> 4;
    float acc[4][4];
    #pragma unroll
    for (int i=0;i<4;i++)
        #pragma unroll
        for (int j=0;j<4;j++) acc[i][j]=0.f;

    for (int k0=0;k0<K;k0+=BK){
        #pragma unroll
        for (int t=0;t<4;t++){
            int i = tid + t*256;
            int m = i >> 4, kk = i & 15;
            int row = bm + m, k = k0 + kk;
            float v = 0.f;
            if (row < M && k < K) v = A[(long)row*lda + k];
            As[kk][m] = v;
            int kk2 = i >> 6, n = i & 63;
            int col = bn + n, k2 = k0 + kk2;
            float w = 0.f;
            if (col < N && k2 < K){
                if (BMODE==0) w = B[(long)k2*ldbk + (long)col*ldbn];
                else          w = (col < HD) ? B[(long)k2*HD + col]
                                             : B2[(long)k2*HD + (col-HD)];
            }
            Bs[kk2][n] = w;
        }
        __syncthreads();
        #pragma unroll
        for (int kk=0;kk<BK;kk++){
            float a0=As[kk][ty*4+0], a1=As[kk][ty*4+1], a2=As[kk][ty*4+2], a3=As[kk][ty*4+3];
            float b0=Bs[kk][tx*4+0], b1=Bs[kk][tx*4+1], b2=Bs[kk][tx*4+2], b3=Bs[kk][tx*4+3];
            acc[0][0]+=a0*b0; acc[0][1]+=a0*b1; acc[0][2]+=a0*b2; acc[0][3]+=a0*b3;
            acc[1][0]+=a1*b0; acc[1][1]+=a1*b1; acc[1][2]+=a1*b2; acc[1][3]+=a1*b3;
            acc[2][0]+=a2*b0; acc[2][1]+=a2*b1; acc[2][2]+=a2*b2; acc[2][3]+=a2*b3;
            acc[3][0]+=a3*b0; acc[3][1]+=a3*b1; acc[3][2]+=a3*b2; acc[3][3]+=a3*b3;
        }
        __syncthreads();
    }
    #pragma unroll
    for (int i=0;i<4;i++){
        int row = bm + ty*4 + i;
        if (row >= M) continue;
        #pragma unroll
        for (int j=0;j<4;j++){
            int col = bn + tx*4 + j;
            if (col >= N) continue;
            float v = acc[i][j];
            if (BMODE==1){ if (bias) v += (col < HD) ? bias[col] : bias2[col-HD]; }
            else if (bias)           v += bias[col];
            if (ACT==1) v = tanhf(v);
            if (ACT==2) v = fmaxf(v, 0.f);
            C[(long)row*ldc + col] = v;
        }
    }
}

// ---------------- GAT pipeline: CSR build + fused online-softmax aggregation ----------------
__global__ void k_init(){
    int i = blockIdx.x*blockDim.x + threadIdx.x;
    if (i < NN){ g_cnt[i] = 1; g_cur[i] = 0; }   // 1 = self loop
    if (i == 0) g_off[NN] = ENE;
}

__global__ void k_count(const int* __restrict__ ei){
    int i = blockIdx.x*blockDim.x + threadIdx.x;
    if (i < EE) atomicAdd(&g_cnt[ei[EE+i]], 1);
}

__global__ void k_scan(){
    __shared__ int sh[1024];
    int t = threadIdx.x;
    const int chunk = (NN + 1023) / 1024;   // 49
    int base = t * chunk;
    int s = 0;
    for (int i=0;i<chunk;i++){ int idx = base+i; if (idx < NN) s += g_cnt[idx]; }
    sh[t] = s; __syncthreads();
    for (int d=1; d<1024; d<<=1){
        int v = (t >= d) ? sh[t-d] : 0;
        __syncthreads();
        sh[t] += v;
        __syncthreads();
    }
    int run = sh[t] - s;   // exclusive prefix
    for (int i=0;i<chunk;i++){
        int idx = base+i;
        if (idx < NN){ g_off[idx] = run; run += g_cnt[idx]; }
    }
}

// scatter src ids into CSR slots (scores computed later, fused into aggregation)
__global__ void k_scatter(const int* __restrict__ ei){
    int i = blockIdx.x*blockDim.x + threadIdx.x;
    if (i >= ENE) return;
    int src, dst;
    if (i < EE){ src = ei[i]; dst = ei[EE+i]; } else { src = dst = i - EE; }
    int pos = g_off[dst] + atomicAdd(&g_cur[dst], 1);
    g_srcs[pos] = src;
}

// warp per dst node: single pass over incident edges with ONLINE softmax + 1-deep
// software pipeline (next src id + xl row loaded before computing current edge).
__global__ void k_aggf(const float* __restrict__ att, const float* __restrict__ gbias){
    int n = blockIdx.x*(blockDim.x>>5) + (threadIdx.x>>5);
    if (n >= NN) return;
    int lane = threadIdx.x & 31;
    float4 xr = *(const float4*)(g_xlr + (long)n*256 + 128 + lane*4);
    float4 at = *(const float4*)(att + lane*4);
    int s0 = g_off[n], s1 = g_off[n+1];
    float m = -1e30f, s = 0.f;
    float4 acc = make_float4(0.f,0.f,0.f,0.f);
    // prologue (every segment has >=1 entry: the self loop)
    int sr = g_srcs[s0];
    float4 xv = *(const float4*)(g_xlr + (long)sr*256 + lane*4);
    for (int j=s0; j<s1; j++){
        float4 nxv = xv;
        if (j+1 < s1){
            int nsr = g_srcs[j+1];                             // independent of compute below
            nxv = *(const float4*)(g_xlr + (long)nsr*256 + lane*4);
        }
        float e = lrelu(xv.x+xr.x)*at.x + lrelu(xv.y+xr.y)*at.y
                + lrelu(xv.z+xr.z)*at.z + lrelu(xv.w+xr.w)*at.w;
        #pragma unroll
        for (int o=16;o;o>>=1) e += __shfl_xor_sync(0xffffffffu, e, o);
        float mn = fmaxf(m, e);
        float sc = expf(m - mn);        // first iter: exp(-inf) = 0
        float w  = expf(e - mn);
        s = s*sc + w;
        acc.x = acc.x*sc + w*xv.x;
        acc.y = acc.y*sc + w*xv.y;
        acc.z = acc.z*sc + w*xv.z;
        acc.w = acc.w*sc + w*xv.w;
        m = mn;
        xv = nxv;
    }
    float inv = 1.f / s;
    float4 bv = *(const float4*)(gbias + lane*4);
    float* op = g_intra + (long)n*HD + lane*4;
    op[0] = tanhf(acc.x*inv + bv.x);
    op[1] = tanhf(acc.y*inv + bv.y);
    op[2] = tanhf(acc.z*inv + bv.z);
    op[3] = tanhf(acc.w*inv + bv.w);
}

// ---------------- transformer helpers ----------------
__global__ void k_gather_c(const int* __restrict__ cn){
    int i = blockIdx.x*blockDim.x + threadIdx.x;
    if (i < GD*HD) g_c[i] = g_intra[(long)cn[i>>7]*HD + (i & 127)];
}

__global__ void k_softmax(){
    int r = blockIdx.x*(blockDim.x>>5) + (threadIdx.x>>5);
    if (r >= 4*GD) return;
    int lane = threadIdx.x & 31;
    float* p = g_sc + (long)r*GD;
    const float scale = 0.17677669529663687f;   // 1/sqrt(32)
    float v[32];
    float m = -1e30f;
    #pragma unroll
    for (int i=0;i<32;i++){ v[i] = p[lane + 32*i] * scale; m = fmaxf(m, v[i]); }
    #pragma unroll
    for (int o=16;o;o>>=1) m = fmaxf(m, __shfl_xor_sync(0xffffffffu, m, o));
    float s = 0.f;
    #pragma unroll
    for (int i=0;i<32;i++){ v[i] = expf(v[i]-m); s += v[i]; }
    #pragma unroll
    for (int o=16;o;o>>=1) s += __shfl_xor_sync(0xffffffffu, s, o);
    float inv = 1.f / s;
    #pragma unroll
    for (int i=0;i<32;i++) p[lane + 32*i] = v[i]*inv;
}

// out = [tanh]( LN(x + y) * g + b ), warp per row of 128
template<int TANH>
__global__ void k_ln(const float* __restrict__ x, const float* __restrict__ y,
                     const float* __restrict__ g, const float* __restrict__ b,
                     float* __restrict__ out, int rows){
    int r = blockIdx.x*(blockDim.x>>5) + (threadIdx.x>>5);
    if (r >= rows) return;
    int lane = threadIdx.x & 31;
    float4 xv = *(const float4*)(x + (long)r*HD + lane*4);
    float4 yv = *(const float4*)(y + (long)r*HD + lane*4);
    float v0 = xv.x+yv.x, v1 = xv.y+yv.y, v2 = xv.z+yv.z, v3 = xv.w+yv.w;
    float s = v0+v1+v2+v3;
    #pragma unroll
    for (int o=16;o;o>>=1) s += __shfl_xor_sync(0xffffffffu, s, o);
    float mu = s * (1.f/128.f);
    float d0=v0-mu, d1=v1-mu, d2=v2-mu, d3=v3-mu;
    float q = d0*d0 + d1*d1 + d2*d2 + d3*d3;
    #pragma unroll
    for (int o=16;o;o>>=1) q += __shfl_xor_sync(0xffffffffu, q, o);
    float rs = rsqrtf(q * (1.f/128.f) + 1e-5f);
    float4 gv = *(const float4*)(g + lane*4);
    float4 bv = *(const float4*)(b + lane*4);
    float o0 = d0*rs*gv.x + bv.x;
    float o1 = d1*rs*gv.y + bv.y;
    float o2 = d2*rs*gv.z + bv.z;
    float o3 = d3*rs*gv.w + bv.w;
    if (TANH){ o0=tanhf(o0); o1=tanhf(o1); o2=tanhf(o2); o3=tanhf(o3); }
    *(float4*)(out + (long)r*HD + lane*4) = make_float4(o0,o1,o2,o3);
}

// ---------------- final heads: warp per node ----------------
__global__ void k_heads(const float* __restrict__ aw2, const float* __restrict__ ab2,
                        const float* __restrict__ vw2, const float* __restrict__ vb2,
                        float* __restrict__ out){
    int n = blockIdx.x*(blockDim.x>>5) + (threadIdx.x>>5);
    if (n >= NN) return;
    int lane = threadIdx.x & 31;
    const float* hp = g_hid + (long)n*256;
    float4 ha = *(const float4*)(hp + lane*4);
    float l[AD];
    #pragma unroll
    for (int j=0;j<AD;j++){
        l[j] = ha.x*aw2[(lane*4+0)*AD+j] + ha.y*aw2[(lane*4+1)*AD+j]
             + ha.z*aw2[(lane*4+2)*AD+j] + ha.w*aw2[(lane*4+3)*AD+j];
    }
    #pragma unroll
    for (int j=0;j<AD;j++)
        #pragma unroll
        for (int o=16;o;o>>=1) l[j] += __shfl_xor_sync(0xffffffffu, l[j], o);
    float4 hv = *(const float4*)(hp + 128 + lane*4);
    float4 wv = *(const float4*)(vw2 + lane*4);
    float v = hv.x*wv.x + hv.y*wv.y + hv.z*wv.z + hv.w*wv.w;
    #pragma unroll
    for (int o=16;o;o>>=1) v += __shfl_xor_sync(0xffffffffu, v, o);
    if (lane == 0){
        float m = -1e30f;
        #pragma unroll
        for (int j=0;j<AD;j++){ l[j] += ab2[j]; m = fmaxf(m, l[j]); }
        float s = 0.f;
        #pragma unroll
        for (int j=0;j<AD;j++) s += expf(l[j]-m);
        float ls = logf(s) + m;
        #pragma unroll
        for (int j=0;j<AD;j++) out[(long)n*AD + j] = l[j] - ls;
        out[(long)NN*AD + n] = v + vb2[0];
    }
}

// ---------------- host ----------------
extern "C" void kernel_launch(void* const* d_in, const int* in_sizes, int n_in,
                              void* d_out, int out_size)
{
    const float* obs  = (const float*)d_in[0];
    const int*   ei   = (const int*)d_in[1];
    const int*   ga   = (const int*)d_in[2];
    const int*   cn   = (const int*)d_in[3];
    const float* embw = (const float*)d_in[4];  const float* embb = (const float*)d_in[5];
    const float* wl   = (const float*)d_in[6];  const float* wr   = (const float*)d_in[7];
    const float* att  = (const float*)d_in[8];  const float* gbias= (const float*)d_in[9];
    const float* ainw = (const float*)d_in[10]; const float* ainb = (const float*)d_in[11];
    const float* aow  = (const float*)d_in[12]; const float* aob  = (const float*)d_in[13];
    const float* ln1g = (const float*)d_in[14]; const float* ln1b = (const float*)d_in[15];
    const float* ln2g = (const float*)d_in[16]; const float* ln2b = (const float*)d_in[17];
    const float* fw1  = (const float*)d_in[18]; const float* fb1  = (const float*)d_in[19];
    const float* fw2  = (const float*)d_in[20]; const float* fb2  = (const float*)d_in[21];
    const float* aw1  = (const float*)d_in[22]; const float* ab1  = (const float*)d_in[23];
    const float* aw2  = (const float*)d_in[24]; const float* ab2  = (const float*)d_in[25];
    const float* vw1  = (const float*)d_in[26]; const float* vb1  = (const float*)d_in[27];
    const float* vw2  = (const float*)d_in[28]; const float* vb2  = (const float*)d_in[29];
    float* out = (float*)d_out;

    void *pv;
    cudaGetSymbolAddress(&pv, g_x);     float* fx    = (float*)pv;
    cudaGetSymbolAddress(&pv, g_xlr);   float* fxlr  = (float*)pv;
    cudaGetSymbolAddress(&pv, g_intra); float* fintra= (float*)pv;
    cudaGetSymbolAddress(&pv, g_hid);   float* fhid  = (float*)pv;
    cudaGetSymbolAddress(&pv, g_c);     float* fc    = (float*)pv;
    cudaGetSymbolAddress(&pv, g_qkv);   float* fqkv  = (float*)pv;
    cudaGetSymbolAddress(&pv, g_sc);    float* fsc   = (float*)pv;
    cudaGetSymbolAddress(&pv, g_o);     float* fo    = (float*)pv;
    cudaGetSymbolAddress(&pv, g_t1);    float* ft1   = (float*)pv;
    cudaGetSymbolAddress(&pv, g_h1);    float* fh1   = (float*)pv;
    cudaGetSymbolAddress(&pv, g_f);     float* ff    = (float*)pv;
    cudaGetSymbolAddress(&pv, g_gobs);  float* fgobs = (float*)pv;
    cudaGetSymbolAddress(&pv, g_pg);    float* fpg   = (float*)pv;

    const int GB = (NN + 127) / 128;   // 391 row blocks for N=50000

    // CSR build (src ids only; scores fused into k_aggf)
    k_init   <<<(NN+255)/256, 256>>>();
    k_count  <<<(EE+255)/256, 256>>>(ei);
    k_scan   <<<1, 1024>>>();
    k_scatter<<<(ENE+255)/256, 256>>>(ei);

    // x = tanh(obs @ emb_w + b)          [50000,256]@[256,128]   (tf32 tensor cores)
    k_tgemm<1><<<dim3(GB,1),256>>>(obs, embw,nullptr, embb,nullptr, nullptr,nullptr,
                                   fx, NN, OBSD, OBSD, HD);
    // [xl|xr] = x @ [Wl|Wr]              [50000,128]@[128,128] x2 (grid.y selects Wl/Wr)
    k_tgemm<0><<<dim3(GB,2),256>>>(fx, wl,wr, nullptr,nullptr, nullptr,nullptr,
                                   fxlr, NN, HD, HD, 2*HD);
    // fused GAT: online-softmax attention + aggregation, one xl load per edge
    k_aggf<<<(NN+7)/8, 256>>>(att, gbias);

    // transformer over core nodes
    k_gather_c<<<(GD*HD+255)/256, 256>>>(cn);
    dim3 g3((GD+63)/64, (3*HD+63)/64);
    k_sgemm<0,0><<<g3,256>>>(fc, ainw,nullptr, ainb,nullptr,
                             fqkv, GD,3*HD,HD, HD,3*HD,1,3*HD, 0,0,0);
    // scores[h] = Q_h @ K_h^T   (grid.z = heads)
    dim3 g4((GD+63)/64, (GD+63)/64, 4);
    k_sgemm<0,0><<<g4,256>>>(fqkv, fqkv+HD,nullptr, nullptr,nullptr,
                             fsc, GD,GD,32, 3*HD,1,3*HD,GD, 32,32,(long)GD*GD);
    k_softmax<<<(4*GD+7)/8, 256>>>();
    // o[h] = attn_h @ V_h
    dim3 g5((GD+63)/64, 1, 4);
    k_sgemm<0,0><<<g5,256>>>(fsc, fqkv+2*HD,nullptr, nullptr,nullptr,
                             fo, GD,32,GD, GD,3*HD,1,HD, (long)GD*GD,32,32);
    // out-proj, LN1, FFN, LN2+tanh
    dim3 g6((GD+63)/64, (HD+63)/64);
    k_sgemm<0,0><<<g6,256>>>(fo, aow,nullptr, aob,nullptr,
                             ft1, GD,HD,HD, HD,HD,1,HD, 0,0,0);
    k_ln<0><<<(GD+7)/8, 256>>>(fc, ft1, ln1g, ln1b, fh1, GD);
    k_sgemm<0,2><<<g6,256>>>(fh1, fw1,nullptr, fb1,nullptr,
                             ff, GD,HD,HD, HD,HD,1,HD, 0,0,0);
    k_sgemm<0,0><<<g6,256>>>(ff, fw2,nullptr, fb2,nullptr,
                             ft1, GD,HD,HD, HD,HD,1,HD, 0,0,0);
    k_ln<1><<<(GD+7)/8, 256>>>(fh1, ft1, ln2g, ln2b, fgobs, GD);

    // PG = gobs @ [actor_w1_top | value_w1_top]   [1024,128]@[128,256] (tiny, fp32)
    dim3 g8((GD+63)/64, (2*HD+63)/64);
    k_sgemm<1,0><<<g8,256>>>(fgobs, aw1,vw1, nullptr,nullptr,
                             fpg, GD,2*HD,HD, HD,0,0,2*HD, 0,0,0);
    // hidden = tanh( intra @ [actor_w1_bot | value_w1_bot] + bias + PG[ga] )
    k_tgemm<3><<<dim3(GB,2),256>>>(fintra, aw1 + HD*HD, vw1 + HD*HD, ab1, vb1,
                                   fpg, ga, fhid, NN, HD, HD, 2*HD);
    // final logits + log_softmax + value
    k_heads<<<(NN+7)/8, 256>>>(aw2, ab2, vw2, vb2, out);
}

// round 13
// speedup vs baseline: 1.9416x; 1.0033x over previous
#include <cuda_runtime.h>
#include <math.h>

#define NN   50000
#define EE   800000
#define OBSD 256
#define HD   128
#define GD   1024
#define AD   10

// ---------------- scratch (static device globals; no allocation) ----------------
__device__ __align__(16) float g_x[NN*HD];          // tanh embedding
__device__ __align__(16) float g_xlr[NN*2*HD];      // [xl | xr] per node
__device__ __align__(16) float g_intra[NN*HD];
__device__ __align__(16) float g_hid[NN*2*HD];      // [actor_hidden | value_hidden]
__device__ __align__(16) int   g_srcs[EE];          // CSR-ordered edge sources (real edges only)
__device__ int   g_cnt[NN];
__device__ int   g_cur[NN];
__device__ int   g_off[NN+1];
__device__ __align__(16) float g_c[GD*HD];
__device__ __align__(16) float g_qkv[GD*3*HD];
__device__ __align__(16) float g_sc[4*GD*GD];
__device__ __align__(16) float g_o[GD*HD];
__device__ __align__(16) float g_t1[GD*HD];
__device__ __align__(16) float g_h1[GD*HD];
__device__ __align__(16) float g_f[GD*HD];
__device__ __align__(16) float g_gobs[GD*HD];
__device__ __align__(16) float g_pg[GD*2*HD];       // gobs @ [actor_w1_top | value_w1_top]

__device__ __forceinline__ float lrelu(float x){ return x > 0.f ? x : 0.2f*x; }

__device__ __forceinline__ unsigned f2tf(float x){
    unsigned u; asm("cvt.rna.tf32.f32 %0, %1;" : "=r"(u) : "f"(x)); return u;
}

__device__ __forceinline__ void mma_tf32(float* d, const unsigned* a, const unsigned* b){
    asm volatile("mma.sync.aligned.m16n8k8.row.col.f32.tf32.tf32.f32 "
        "{%0,%1,%2,%3}, {%4,%5,%6,%7}, {%8,%9}, {%0,%1,%2,%3};"
        : "+f"(d[0]), "+f"(d[1]), "+f"(d[2]), "+f"(d[3])
        : "r"(a[0]), "r"(a[1]), "r"(a[2]), "r"(a[3]), "r"(b[0]), "r"(b[1]));
}

// ============ tf32 tensor-core GEMM: 128x128 CTA tile, 8 warps (2x4), 64x32/warp ============
// C[row, bn+col] = epi( A[row,:K] @ B[:,col] + bias[col] (+ PG[gidx[row]*256+bn+col]) )
// B selected per blockIdx.y: y==0 -> B0/bias0, y==1 -> B1/bias1.  B layout B[k*128+col].
// EPI: 0 none, 1 tanh, 3 tanh + PG gather add.   K must be a multiple of 16.
template<int EPI>
__global__ __launch_bounds__(256) void k_tgemm(
    const float* __restrict__ A,
    const float* __restrict__ B0, const float* __restrict__ B1,
    const float* __restrict__ bias0, const float* __restrict__ bias1,
    const float* __restrict__ PG, const int* __restrict__ gidx,
    float* __restrict__ C,
    int M, int K, int lda, int ldc)
{
    __shared__ __align__(16) unsigned As[16][136];   // [k][row], pad -> frag loads conflict-free
    __shared__ __align__(16) unsigned Bs[16][136];   // [k][col]
    const float* B    = blockIdx.y ? B1 : B0;
    const float* bias = blockIdx.y ? bias1 : bias0;
    const int bn = blockIdx.y * 128;
    const int bm = blockIdx.x * 128;
    const int tid = threadIdx.x;

    const int arow = tid >> 1;
    const int akk  = (tid & 1) * 8;
    const int grow = bm + arow;
    const bool rok = (grow < M);
    const float* Ap = A + (long)grow * lda;
    const int bkk  = tid >> 5;
    const int bcol = (tid & 31) * 4;

    const int lane = tid & 31;
    const int gid  = lane >> 2;        // 0..7
    const int tig  = lane & 3;         // 0..3
    const int w    = tid >> 5;         // warp 0..7
    const int wm   = (w >> 2) * 64;    // warp row offset in tile
    const int wn   = (w & 3) * 32;     // warp col offset in tile

    float d[4][4][4];
    #pragma unroll
    for (int mi=0;mi<4;mi++)
        #pragma unroll
        for (int nj=0;nj<4;nj++)
            #pragma unroll
            for (int q=0;q<4;q++) d[mi][nj][q] = 0.f;

    float4 av0 = make_float4(0,0,0,0), av1 = make_float4(0,0,0,0);
    if (rok){
        av0 = *(const float4*)(Ap + akk);
        av1 = *(const float4*)(Ap + akk + 4);
    }
    float4 bv0 = *(const float4*)(B + (long)(bkk  )*128 + bcol);
    float4 bv1 = *(const float4*)(B + (long)(bkk+8)*128 + bcol);

    for (int k0=0; k0<K; k0+=16){
        As[akk+0][arow]=f2tf(av0.x); As[akk+1][arow]=f2tf(av0.y);
        As[akk+2][arow]=f2tf(av0.z); As[akk+3][arow]=f2tf(av0.w);
        As[akk+4][arow]=f2tf(av1.x); As[akk+5][arow]=f2tf(av1.y);
        As[akk+6][arow]=f2tf(av1.z); As[akk+7][arow]=f2tf(av1.w);
        // packed 128-bit stores -> conflict-free (was 8-way conflicted scalar stores)
        *(uint4*)&Bs[bkk  ][bcol] = make_uint4(f2tf(bv0.x), f2tf(bv0.y), f2tf(bv0.z), f2tf(bv0.w));
        *(uint4*)&Bs[bkk+8][bcol] = make_uint4(f2tf(bv1.x), f2tf(bv1.y), f2tf(bv1.z), f2tf(bv1.w));
        __syncthreads();
        // prefetch next tile (overlaps with mma below)
        float4 na0 = make_float4(0,0,0,0), na1 = make_float4(0,0,0,0);
        float4 nb0 = make_float4(0,0,0,0), nb1 = make_float4(0,0,0,0);
        if (k0 + 16 < K){
            if (rok){
                na0 = *(const float4*)(Ap + k0 + 16 + akk);
                na1 = *(const float4*)(Ap + k0 + 16 + akk + 4);
            }
            nb0 = *(const float4*)(B + (long)(k0+16+bkk  )*128 + bcol);
            nb1 = *(const float4*)(B + (long)(k0+16+bkk+8)*128 + bcol);
        }
        #pragma unroll
        for (int k8=0; k8<16; k8+=8){
            unsigned af[4][4], bf[4][2];
            #pragma unroll
            for (int mi=0;mi<4;mi++){
                int r0 = wm + 16*mi + gid;
                af[mi][0] = As[k8+tig  ][r0];
                af[mi][1] = As[k8+tig  ][r0+8];
                af[mi][2] = As[k8+tig+4][r0];
                af[mi][3] = As[k8+tig+4][r0+8];
            }
            #pragma unroll
            for (int nj=0;nj<4;nj++){
                int c0 = wn + 8*nj + gid;
                bf[nj][0] = Bs[k8+tig  ][c0];
                bf[nj][1] = Bs[k8+tig+4][c0];
            }
            #pragma unroll
            for (int mi=0;mi<4;mi++)
                #pragma unroll
                for (int nj=0;nj<4;nj++)
                    mma_tf32(d[mi][nj], af[mi], bf[nj]);
        }
        __syncthreads();
        av0 = na0; av1 = na1; bv0 = nb0; bv1 = nb1;
    }

    #pragma unroll
    for (int mi=0;mi<4;mi++){
        int r0 = bm + wm + 16*mi + gid;
        int r1 = r0 + 8;
        int gi0 = 0, gi1 = 0;
        if (EPI==3){
            if (r0 < M) gi0 = gidx[r0];
            if (r1 < M) gi1 = gidx[r1];
        }
        #pragma unroll
        for (int nj=0;nj<4;nj++){
            int lc = wn + 8*nj + 2*tig;
            float b0v = bias ? bias[lc]   : 0.f;
            float b1v = bias ? bias[lc+1] : 0.f;
            if (r0 < M){
                float v0 = d[mi][nj][0] + b0v;
                float v1 = d[mi][nj][1] + b1v;
                if (EPI==3){
                    v0 += PG[(long)gi0*256 + bn + lc];
                    v1 += PG[(long)gi0*256 + bn + lc + 1];
                }
                if (EPI==1 || EPI==3){ v0 = tanhf(v0); v1 = tanhf(v1); }
                *(float2*)(C + (long)r0*ldc + bn + lc) = make_float2(v0, v1);
            }
            if (r1 < M){
                float v2 = d[mi][nj][2] + b0v;
                float v3 = d[mi][nj][3] + b1v;
                if (EPI==3){
                    v2 += PG[(long)gi1*256 + bn + lc];
                    v3 += PG[(long)gi1*256 + bn + lc + 1];
                }
                if (EPI==1 || EPI==3){ v2 = tanhf(v2); v3 = tanhf(v3); }
                *(float2*)(C + (long)r1*ldc + bn + lc) = make_float2(v2, v3);
            }
        }
    }
}

// ---------------- generic tiled SGEMM (64x64), kept for small/odd shapes ----------------
template<int BMODE,int ACT>
__global__ __launch_bounds__(256) void k_sgemm(
    const float* __restrict__ A,
    const float* __restrict__ B, const float* __restrict__ B2,
    const float* __restrict__ bias, const float* __restrict__ bias2,
    float* __restrict__ C,
    int M, int N, int K, int lda, int ldbk, int ldbn, int ldc,
    long zA, long zB, long zC)
{
    const int BM=64, BN=64, BK=16;
    __shared__ float As[BK][BM+4];
    __shared__ float Bs[BK][BN+4];
    A += (long)blockIdx.z * zA;
    B += (long)blockIdx.z * zB;
    C += (long)blockIdx.z * zC;
    int bm = blockIdx.x*BM, bn = blockIdx.y*BN;
    int tid = threadIdx.x;
    int tx = tid & 15, ty = tid >> 4;
    float acc[4][4];
    #pragma unroll
    for (int i=0;i<4;i++)
        #pragma unroll
        for (int j=0;j<4;j++) acc[i][j]=0.f;

    for (int k0=0;k0<K;k0+=BK){
        #pragma unroll
        for (int t=0;t<4;t++){
            int i = tid + t*256;
            int m = i >> 4, kk = i & 15;
            int row = bm + m, k = k0 + kk;
            float v = 0.f;
            if (row < M && k < K) v = A[(long)row*lda + k];
            As[kk][m] = v;
            int kk2 = i >> 6, n = i & 63;
            int col = bn + n, k2 = k0 + kk2;
            float w = 0.f;
            if (col < N && k2 < K){
                if (BMODE==0) w = B[(long)k2*ldbk + (long)col*ldbn];
                else          w = (col < HD) ? B[(long)k2*HD + col]
                                             : B2[(long)k2*HD + (col-HD)];
            }
            Bs[kk2][n] = w;
        }
        __syncthreads();
        #pragma unroll
        for (int kk=0;kk<BK;kk++){
            float a0=As[kk][ty*4+0], a1=As[kk][ty*4+1], a2=As[kk][ty*4+2], a3=As[kk][ty*4+3];
            float b0=Bs[kk][tx*4+0], b1=Bs[kk][tx*4+1], b2=Bs[kk][tx*4+2], b3=Bs[kk][tx*4+3];
            acc[0][0]+=a0*b0; acc[0][1]+=a0*b1; acc[0][2]+=a0*b2; acc[0][3]+=a0*b3;
            acc[1][0]+=a1*b0; acc[1][1]+=a1*b1; acc[1][2]+=a1*b2; acc[1][3]+=a1*b3;
            acc[2][0]+=a2*b0; acc[2][1]+=a2*b1; acc[2][2]+=a2*b2; acc[2][3]+=a2*b3;
            acc[3][0]+=a3*b0; acc[3][1]+=a3*b1; acc[3][2]+=a3*b2; acc[3][3]+=a3*b3;
        }
        __syncthreads();
    }
    #pragma unroll
    for (int i=0;i<4;i++){
        int row = bm + ty*4 + i;
        if (row >= M) continue;
        #pragma unroll
        for (int j=0;j<4;j++){
            int col = bn + tx*4 + j;
            if (col >= N) continue;
            float v = acc[i][j];
            if (BMODE==1){ if (bias) v += (col < HD) ? bias[col] : bias2[col-HD]; }
            else if (bias)           v += bias[col];
            if (ACT==1) v = tanhf(v);
            if (ACT==2) v = fmaxf(v, 0.f);
            C[(long)row*ldc + col] = v;
        }
    }
}

// ---------------- GAT pipeline: CSR build (real edges only) ----------------
__global__ void k_init(){
    int i = blockIdx.x*blockDim.x + threadIdx.x;
    if (i < NN){ g_cnt[i] = 0; g_cur[i] = 0; }
    if (i == 0) g_off[NN] = EE;
}

__global__ void k_count(const int* __restrict__ ei){
    int i = blockIdx.x*blockDim.x + threadIdx.x;
    if (i < EE) atomicAdd(&g_cnt[ei[EE+i]], 1);
}

__global__ void k_scan(){
    __shared__ int sh[1024];
    int t = threadIdx.x;
    const int chunk = (NN + 1023) / 1024;   // 49
    int base = t * chunk;
    int s = 0;
    for (int i=0;i<chunk;i++){ int idx = base+i; if (idx < NN) s += g_cnt[idx]; }
    sh[t] = s; __syncthreads();
    for (int d=1; d<1024; d<<=1){
        int v = (t >= d) ? sh[t-d] : 0;
        __syncthreads();
        sh[t] += v;
        __syncthreads();
    }
    int run = sh[t] - s;   // exclusive prefix
    for (int i=0;i<chunk;i++){
        int idx = base+i;
        if (idx < NN){ g_off[idx] = run; run += g_cnt[idx]; }
    }
}

__global__ void k_scatter(const int* __restrict__ ei){
    int i = blockIdx.x*blockDim.x + threadIdx.x;
    if (i >= EE) return;
    int src = ei[i], dst = ei[EE+i];
    int pos = g_off[dst] + atomicAdd(&g_cur[dst], 1);
    g_srcs[pos] = src;
}

// warp per dst node: online-softmax GAT with a 2-deep software pipeline.
// Self-loop handled analytically in the prologue (initializes m/s/acc).
// Loop-carried chain is only the (m,s,acc) update; the shfl score-reduction of
// edge j+1 and the xl load of edge j+2 overlap with the update of edge j.
__global__ void k_aggf(const float* __restrict__ att, const float* __restrict__ gbias){
    int n = blockIdx.x*(blockDim.x>>5) + (threadIdx.x>>5);
    if (n >= NN) return;
    int lane = threadIdx.x & 31;
    float4 xs = *(const float4*)(g_xlr + (long)n*256 + lane*4);         // xl[n]
    float4 xr = *(const float4*)(g_xlr + (long)n*256 + 128 + lane*4);   // xr[n]
    float4 at = *(const float4*)(att + lane*4);

    // self-loop: w = exp(e_self - m) = 1
    float e = lrelu(xs.x+xr.x)*at.x + lrelu(xs.y+xr.y)*at.y
            + lrelu(xs.z+xr.z)*at.z + lrelu(xs.w+xr.w)*at.w;
    #pragma unroll
    for (int o=16;o;o>>=1) e += __shfl_xor_sync(0xffffffffu, e, o);
    float m = e, s = 1.f;
    float4 acc = xs;

    int s0 = g_off[n], s1 = g_off[n+1];
    if (s0 < s1){
        int i1 = min(s0+1, s1-1);
        float4 xva = *(const float4*)(g_xlr + (long)g_srcs[s0]*256 + lane*4); // xv_j
        float4 xvb = *(const float4*)(g_xlr + (long)g_srcs[i1]*256 + lane*4); // xv_{j+1}
        float ec = lrelu(xva.x+xr.x)*at.x + lrelu(xva.y+xr.y)*at.y
                 + lrelu(xva.z+xr.z)*at.z + lrelu(xva.w+xr.w)*at.w;
        #pragma unroll
        for (int o=16;o;o>>=1) ec += __shfl_xor_sync(0xffffffffu, ec, o);
        for (int j=s0; j<s1; j++){
            // stage 1: prefetch xv_{j+2}
            int jn = min(j+2, s1-1);
            float4 xvc = *(const float4*)(g_xlr + (long)g_srcs[jn]*256 + lane*4);
            // stage 2: score of edge j+1 (independent of the update below)
            float en = lrelu(xvb.x+xr.x)*at.x + lrelu(xvb.y+xr.y)*at.y
                     + lrelu(xvb.z+xr.z)*at.z + lrelu(xvb.w+xr.w)*at.w;
            #pragma unroll
            for (int o=16;o;o>>=1) en += __shfl_xor_sync(0xffffffffu, en, o);
            // stage 3: update with edge j
            float mn = fmaxf(m, ec);
            float sc = __expf(m - mn);
            float w  = __expf(ec - mn);
            s = s*sc + w;
            acc.x = acc.x*sc + w*xva.x;
            acc.y = acc.y*sc + w*xva.y;
            acc.z = acc.z*sc + w*xva.z;
            acc.w = acc.w*sc + w*xva.w;
            m = mn;
            xva = xvb; xvb = xvc; ec = en;
        }
    }
    float inv = 1.f / s;
    float4 bv = *(const float4*)(gbias + lane*4);
    float* op = g_intra + (long)n*HD + lane*4;
    op[0] = tanhf(acc.x*inv + bv.x);
    op[1] = tanhf(acc.y*inv + bv.y);
    op[2] = tanhf(acc.z*inv + bv.z);
    op[3] = tanhf(acc.w*inv + bv.w);
}

// ---------------- transformer helpers ----------------
__global__ void k_gather_c(const int* __restrict__ cn){
    int i = blockIdx.x*blockDim.x + threadIdx.x;
    if (i < GD*HD) g_c[i] = g_intra[(long)cn[i>>7]*HD + (i & 127)];
}

__global__ void k_softmax(){
    int r = blockIdx.x*(blockDim.x>>5) + (threadIdx.x>>5);
    if (r >= 4*GD) return;
    int lane = threadIdx.x & 31;
    float* p = g_sc + (long)r*GD;
    const float scale = 0.17677669529663687f;   // 1/sqrt(32)
    float v[32];
    float m = -1e30f;
    #pragma unroll
    for (int i=0;i<32;i++){ v[i] = p[lane + 32*i] * scale; m = fmaxf(m, v[i]); }
    #pragma unroll
    for (int o=16;o;o>>=1) m = fmaxf(m, __shfl_xor_sync(0xffffffffu, m, o));
    float s = 0.f;
    #pragma unroll
    for (int i=0;i<32;i++){ v[i] = __expf(v[i]-m); s += v[i]; }
    #pragma unroll
    for (int o=16;o;o>>=1) s += __shfl_xor_sync(0xffffffffu, s, o);
    float inv = 1.f / s;
    #pragma unroll
    for (int i=0;i<32;i++) p[lane + 32*i] = v[i]*inv;
}

// out = [tanh]( LN(x + y) * g + b ), warp per row of 128
template<int TANH>
__global__ void k_ln(const float* __restrict__ x, const float* __restrict__ y,
                     const float* __restrict__ g, const float* __restrict__ b,
                     float* __restrict__ out, int rows){
    int r = blockIdx.x*(blockDim.x>>5) + (threadIdx.x>>5);
    if (r >= rows) return;
    int lane = threadIdx.x & 31;
    float4 xv = *(const float4*)(x + (long)r*HD + lane*4);
    float4 yv = *(const float4*)(y + (long)r*HD + lane*4);
    float v0 = xv.x+yv.x, v1 = xv.y+yv.y, v2 = xv.z+yv.z, v3 = xv.w+yv.w;
    float s = v0+v1+v2+v3;
    #pragma unroll
    for (int o=16;o;o>>=1) s += __shfl_xor_sync(0xffffffffu, s, o);
    float mu = s * (1.f/128.f);
    float d0=v0-mu, d1=v1-mu, d2=v2-mu, d3=v3-mu;
    float q = d0*d0 + d1*d1 + d2*d2 + d3*d3;
    #pragma unroll
    for (int o=16;o;o>>=1) q += __shfl_xor_sync(0xffffffffu, q, o);
    float rs = rsqrtf(q * (1.f/128.f) + 1e-5f);
    float4 gv = *(const float4*)(g + lane*4);
    float4 bv = *(const float4*)(b + lane*4);
    float o0 = d0*rs*gv.x + bv.x;
    float o1 = d1*rs*gv.y + bv.y;
    float o2 = d2*rs*gv.z + bv.z;
    float o3 = d3*rs*gv.w + bv.w;
    if (TANH){ o0=tanhf(o0); o1=tanhf(o1); o2=tanhf(o2); o3=tanhf(o3); }
    *(float4*)(out + (long)r*HD + lane*4) = make_float4(o0,o1,o2,o3);
}

// ---------------- final heads: warp per node ----------------
__global__ void k_heads(const float* __restrict__ aw2, const float* __restrict__ ab2,
                        const float* __restrict__ vw2, const float* __restrict__ vb2,
                        float* __restrict__ out){
    int n = blockIdx.x*(blockDim.x>>5) + (threadIdx.x>>5);
    if (n >= NN) return;
    int lane = threadIdx.x & 31;
    const float* hp = g_hid + (long)n*256;
    float4 ha = *(const float4*)(hp + lane*4);
    float l[AD];
    #pragma unroll
    for (int j=0;j<AD;j++){
        l[j] = ha.x*aw2[(lane*4+0)*AD+j] + ha.y*aw2[(lane*4+1)*AD+j]
             + ha.z*aw2[(lane*4+2)*AD+j] + ha.w*aw2[(lane*4+3)*AD+j];
    }
    #pragma unroll
    for (int j=0;j<AD;j++)
        #pragma unroll
        for (int o=16;o;o>>=1) l[j] += __shfl_xor_sync(0xffffffffu, l[j], o);
    float4 hv = *(const float4*)(hp + 128 + lane*4);
    float4 wv = *(const float4*)(vw2 + lane*4);
    float v = hv.x*wv.x + hv.y*wv.y + hv.z*wv.z + hv.w*wv.w;
    #pragma unroll
    for (int o=16;o;o>>=1) v += __shfl_xor_sync(0xffffffffu, v, o);
    if (lane == 0){
        float m = -1e30f;
        #pragma unroll
        for (int j=0;j<AD;j++){ l[j] += ab2[j]; m = fmaxf(m, l[j]); }
        float s = 0.f;
        #pragma unroll
        for (int j=0;j<AD;j++) s += expf(l[j]-m);
        float ls = logf(s) + m;
        #pragma unroll
        for (int j=0;j<AD;j++) out[(long)n*AD + j] = l[j] - ls;
        out[(long)NN*AD + n] = v + vb2[0];
    }
}

// ---------------- host ----------------
extern "C" void kernel_launch(void* const* d_in, const int* in_sizes, int n_in,
                              void* d_out, int out_size)
{
    const float* obs  = (const float*)d_in[0];
    const int*   ei   = (const int*)d_in[1];
    const int*   ga   = (const int*)d_in[2];
    const int*   cn   = (const int*)d_in[3];
    const float* embw = (const float*)d_in[4];  const float* embb = (const float*)d_in[5];
    const float* wl   = (const float*)d_in[6];  const float* wr   = (const float*)d_in[7];
    const float* att  = (const float*)d_in[8];  const float* gbias= (const float*)d_in[9];
    const float* ainw = (const float*)d_in[10]; const float* ainb = (const float*)d_in[11];
    const float* aow  = (const float*)d_in[12]; const float* aob  = (const float*)d_in[13];
    const float* ln1g = (const float*)d_in[14]; const float* ln1b = (const float*)d_in[15];
    const float* ln2g = (const float*)d_in[16]; const float* ln2b = (const float*)d_in[17];
    const float* fw1  = (const float*)d_in[18]; const float* fb1  = (const float*)d_in[19];
    const float* fw2  = (const float*)d_in[20]; const float* fb2  = (const float*)d_in[21];
    const float* aw1  = (const float*)d_in[22]; const float* ab1  = (const float*)d_in[23];
    const float* aw2  = (const float*)d_in[24]; const float* ab2  = (const float*)d_in[25];
    const float* vw1  = (const float*)d_in[26]; const float* vb1  = (const float*)d_in[27];
    const float* vw2  = (const float*)d_in[28]; const float* vb2  = (const float*)d_in[29];
    float* out = (float*)d_out;

    void *pv;
    cudaGetSymbolAddress(&pv, g_x);     float* fx    = (float*)pv;
    cudaGetSymbolAddress(&pv, g_xlr);   float* fxlr  = (float*)pv;
    cudaGetSymbolAddress(&pv, g_intra); float* fintra= (float*)pv;
    cudaGetSymbolAddress(&pv, g_hid);   float* fhid  = (float*)pv;
    cudaGetSymbolAddress(&pv, g_c);     float* fc    = (float*)pv;
    cudaGetSymbolAddress(&pv, g_qkv);   float* fqkv  = (float*)pv;
    cudaGetSymbolAddress(&pv, g_sc);    float* fsc   = (float*)pv;
    cudaGetSymbolAddress(&pv, g_o);     float* fo    = (float*)pv;
    cudaGetSymbolAddress(&pv, g_t1);    float* ft1   = (float*)pv;
    cudaGetSymbolAddress(&pv, g_h1);    float* fh1   = (float*)pv;
    cudaGetSymbolAddress(&pv, g_f);     float* ff    = (float*)pv;
    cudaGetSymbolAddress(&pv, g_gobs);  float* fgobs = (float*)pv;
    cudaGetSymbolAddress(&pv, g_pg);    float* fpg   = (float*)pv;

    const int GB = (NN + 127) / 128;   // 391 row blocks for N=50000

    // CSR build (real edges only; self loops handled analytically in k_aggf)
    k_init   <<<(NN+255)/256, 256>>>();
    k_count  <<<(EE+255)/256, 256>>>(ei);
    k_scan   <<<1, 1024>>>();
    k_scatter<<<(EE+255)/256, 256>>>(ei);

    // x = tanh(obs @ emb_w + b)          [50000,256]@[256,128]   (tf32 tensor cores)
    k_tgemm<1><<<dim3(GB,1),256>>>(obs, embw,nullptr, embb,nullptr, nullptr,nullptr,
                                   fx, NN, OBSD, OBSD, HD);
    // [xl|xr] = x @ [Wl|Wr]              [50000,128]@[128,128] x2 (grid.y selects Wl/Wr)
    k_tgemm<0><<<dim3(GB,2),256>>>(fx, wl,wr, nullptr,nullptr, nullptr,nullptr,
                                   fxlr, NN, HD, HD, 2*HD);
    // fused GAT: pipelined online-softmax attention + aggregation
    k_aggf<<<(NN+7)/8, 256>>>(att, gbias);

    // transformer over core nodes
    k_gather_c<<<(GD*HD+255)/256, 256>>>(cn);
    dim3 g3((GD+63)/64, (3*HD+63)/64);
    k_sgemm<0,0><<<g3,256>>>(fc, ainw,nullptr, ainb,nullptr,
                             fqkv, GD,3*HD,HD, HD,3*HD,1,3*HD, 0,0,0);
    // scores[h] = Q_h @ K_h^T   (grid.z = heads)
    dim3 g4((GD+63)/64, (GD+63)/64, 4);
    k_sgemm<0,0><<<g4,256>>>(fqkv, fqkv+HD,nullptr, nullptr,nullptr,
                             fsc, GD,GD,32, 3*HD,1,3*HD,GD, 32,32,(long)GD*GD);
    k_softmax<<<(4*GD+7)/8, 256>>>();
    // o[h] = attn_h @ V_h
    dim3 g5((GD+63)/64, 1, 4);
    k_sgemm<0,0><<<g5,256>>>(fsc, fqkv+2*HD,nullptr, nullptr,nullptr,
                             fo, GD,32,GD, GD,3*HD,1,HD, (long)GD*GD,32,32);
    // out-proj, LN1, FFN, LN2+tanh
    dim3 g6((GD+63)/64, (HD+63)/64);
    k_sgemm<0,0><<<g6,256>>>(fo, aow,nullptr, aob,nullptr,
                             ft1, GD,HD,HD, HD,HD,1,HD, 0,0,0);
    k_ln<0><<<(GD+7)/8, 256>>>(fc, ft1, ln1g, ln1b, fh1, GD);
    k_sgemm<0,2><<<g6,256>>>(fh1, fw1,nullptr, fb1,nullptr,
                             ff, GD,HD,HD, HD,HD,1,HD, 0,0,0);
    k_sgemm<0,0><<<g6,256>>>(ff, fw2,nullptr, fb2,nullptr,
                             ft1, GD,HD,HD, HD,HD,1,HD, 0,0,0);
    k_ln<1><<<(GD+7)/8, 256>>>(fh1, ft1, ln2g, ln2b, fgobs, GD);

    // PG = gobs @ [actor_w1_top | value_w1_top]   [1024,128]@[128,256] (tiny, fp32)
    dim3 g8((GD+63)/64, (2*HD+63)/64);
    k_sgemm<1,0><<<g8,256>>>(fgobs, aw1,vw1, nullptr,nullptr,
                             fpg, GD,2*HD,HD, HD,0,0,2*HD, 0,0,0);
    // hidden = tanh( intra @ [actor_w1_bot | value_w1_bot] + bias + PG[ga] )
    k_tgemm<3><<<dim3(GB,2),256>>>(fintra, aw1 + HD*HD, vw1 + HD*HD, ab1, vb1,
                                   fpg, ga, fhid, NN, HD, HD, 2*HD);
    // final logits + log_softmax + value
    k_heads<<<(NN+7)/8, 256>>>(aw2, ab2, vw2, vb2, out);
}

// round 14
// speedup vs baseline: 2.4436x; 1.2585x over previous
#include <cuda_runtime.h>
#include <math.h>

#define NN   50000
#define EE   800000
#define OBSD 256
#define HD   128
#define GD   1024
#define NH   4
#define AD   10

// ---------------- scratch (static device globals; no allocation) ----------------
__device__ __align__(16) float g_x[NN*HD];          // tanh embedding
__device__ __align__(16) float g_xlr[NN*2*HD];      // [xl | xr] per node
__device__ __align__(16) float g_intra[NN*HD];
__device__ __align__(16) float g_hid[NN*2*HD];      // [actor_hidden | value_hidden]
__device__ __align__(16) int   g_srcs[EE];          // CSR-ordered edge sources
__device__ int   g_cnt[NN];
__device__ int   g_cur[NN];
__device__ int   g_off[NN+1];
__device__ __align__(16) float g_qkv[GD*3*HD];
__device__ __align__(16) float g_sc[NH*GD*GD];      // raw attention scores
__device__ __align__(16) float g_o[GD*HD];
__device__ __align__(16) float g_t1[GD*HD];
__device__ __align__(16) float g_h1[GD*HD];
__device__ __align__(16) float g_f[GD*HD];
__device__ __align__(16) float g_gobs[GD*HD];
__device__ __align__(16) float g_pg[GD*2*HD];       // gobs @ [actor_w1_top | value_w1_top]

__device__ __forceinline__ float lrelu(float x){ return x > 0.f ? x : 0.2f*x; }

__device__ __forceinline__ unsigned f2tf(float x){
    unsigned u; asm("cvt.rna.tf32.f32 %0, %1;" : "=r"(u) : "f"(x)); return u;
}

__device__ __forceinline__ void mma_tf32(float* d, const unsigned* a, const unsigned* b){
    asm volatile("mma.sync.aligned.m16n8k8.row.col.f32.tf32.tf32.f32 "
        "{%0,%1,%2,%3}, {%4,%5,%6,%7}, {%8,%9}, {%0,%1,%2,%3};"
        : "+f"(d[0]), "+f"(d[1]), "+f"(d[2]), "+f"(d[3])
        : "r"(a[0]), "r"(a[1]), "r"(a[2]), "r"(a[3]), "r"(b[0]), "r"(b[1]));
}

// ============ tf32 tensor-core GEMM: 128x128 CTA tile, 8 warps (2x4), 64x32/warp ============
template<int EPI>
__global__ __launch_bounds__(256) void k_tgemm(
    const float* __restrict__ A,
    const float* __restrict__ B0, const float* __restrict__ B1,
    const float* __restrict__ bias0, const float* __restrict__ bias1,
    const float* __restrict__ PG, const int* __restrict__ gidx,
    float* __restrict__ C,
    int M, int K, int lda, int ldc)
{
    __shared__ __align__(16) unsigned As[16][136];
    __shared__ __align__(16) unsigned Bs[16][136];
    const float* B    = blockIdx.y ? B1 : B0;
    const float* bias = blockIdx.y ? bias1 : bias0;
    const int bn = blockIdx.y * 128;
    const int bm = blockIdx.x * 128;
    const int tid = threadIdx.x;

    const int arow = tid >> 1;
    const int akk  = (tid & 1) * 8;
    const int grow = bm + arow;
    const bool rok = (grow < M);
    const float* Ap = A + (long)grow * lda;
    const int bkk  = tid >> 5;
    const int bcol = (tid & 31) * 4;

    const int lane = tid & 31;
    const int gid  = lane >> 2;
    const int tig  = lane & 3;
    const int w    = tid >> 5;
    const int wm   = (w >> 2) * 64;
    const int wn   = (w & 3) * 32;

    float d[4][4][4];
    #pragma unroll
    for (int mi=0;mi<4;mi++)
        #pragma unroll
        for (int nj=0;nj<4;nj++)
            #pragma unroll
            for (int q=0;q<4;q++) d[mi][nj][q] = 0.f;

    float4 av0 = make_float4(0,0,0,0), av1 = make_float4(0,0,0,0);
    if (rok){
        av0 = *(const float4*)(Ap + akk);
        av1 = *(const float4*)(Ap + akk + 4);
    }
    float4 bv0 = *(const float4*)(B + (long)(bkk  )*128 + bcol);
    float4 bv1 = *(const float4*)(B + (long)(bkk+8)*128 + bcol);

    for (int k0=0; k0<K; k0+=16){
        As[akk+0][arow]=f2tf(av0.x); As[akk+1][arow]=f2tf(av0.y);
        As[akk+2][arow]=f2tf(av0.z); As[akk+3][arow]=f2tf(av0.w);
        As[akk+4][arow]=f2tf(av1.x); As[akk+5][arow]=f2tf(av1.y);
        As[akk+6][arow]=f2tf(av1.z); As[akk+7][arow]=f2tf(av1.w);
        *(uint4*)&Bs[bkk  ][bcol] = make_uint4(f2tf(bv0.x), f2tf(bv0.y), f2tf(bv0.z), f2tf(bv0.w));
        *(uint4*)&Bs[bkk+8][bcol] = make_uint4(f2tf(bv1.x), f2tf(bv1.y), f2tf(bv1.z), f2tf(bv1.w));
        __syncthreads();
        float4 na0 = make_float4(0,0,0,0), na1 = make_float4(0,0,0,0);
        float4 nb0 = make_float4(0,0,0,0), nb1 = make_float4(0,0,0,0);
        if (k0 + 16 < K){
            if (rok){
                na0 = *(const float4*)(Ap + k0 + 16 + akk);
                na1 = *(const float4*)(Ap + k0 + 16 + akk + 4);
            }
            nb0 = *(const float4*)(B + (long)(k0+16+bkk  )*128 + bcol);
            nb1 = *(const float4*)(B + (long)(k0+16+bkk+8)*128 + bcol);
        }
        #pragma unroll
        for (int k8=0; k8<16; k8+=8){
            unsigned af[4][4], bf[4][2];
            #pragma unroll
            for (int mi=0;mi<4;mi++){
                int r0 = wm + 16*mi + gid;
                af[mi][0] = As[k8+tig  ][r0];
                af[mi][1] = As[k8+tig  ][r0+8];
                af[mi][2] = As[k8+tig+4][r0];
                af[mi][3] = As[k8+tig+4][r0+8];
            }
            #pragma unroll
            for (int nj=0;nj<4;nj++){
                int c0 = wn + 8*nj + gid;
                bf[nj][0] = Bs[k8+tig  ][c0];
                bf[nj][1] = Bs[k8+tig+4][c0];
            }
            #pragma unroll
            for (int mi=0;mi<4;mi++)
                #pragma unroll
                for (int nj=0;nj<4;nj++)
                    mma_tf32(d[mi][nj], af[mi], bf[nj]);
        }
        __syncthreads();
        av0 = na0; av1 = na1; bv0 = nb0; bv1 = nb1;
    }

    #pragma unroll
    for (int mi=0;mi<4;mi++){
        int r0 = bm + wm + 16*mi + gid;
        int r1 = r0 + 8;
        int gi0 = 0, gi1 = 0;
        if (EPI==3){
            if (r0 < M) gi0 = gidx[r0];
            if (r1 < M) gi1 = gidx[r1];
        }
        #pragma unroll
        for (int nj=0;nj<4;nj++){
            int lc = wn + 8*nj + 2*tig;
            float b0v = bias ? bias[lc]   : 0.f;
            float b1v = bias ? bias[lc+1] : 0.f;
            if (r0 < M){
                float v0 = d[mi][nj][0] + b0v;
                float v1 = d[mi][nj][1] + b1v;
                if (EPI==3){
                    v0 += PG[(long)gi0*256 + bn + lc];
                    v1 += PG[(long)gi0*256 + bn + lc + 1];
                }
                if (EPI==1 || EPI==3){ v0 = tanhf(v0); v1 = tanhf(v1); }
                *(float2*)(C + (long)r0*ldc + bn + lc) = make_float2(v0, v1);
            }
            if (r1 < M){
                float v2 = d[mi][nj][2] + b0v;
                float v3 = d[mi][nj][3] + b1v;
                if (EPI==3){
                    v2 += PG[(long)gi1*256 + bn + lc];
                    v3 += PG[(long)gi1*256 + bn + lc + 1];
                }
                if (EPI==1 || EPI==3){ v2 = tanhf(v2); v3 = tanhf(v3); }
                *(float2*)(C + (long)r1*ldc + bn + lc) = make_float2(v2, v3);
            }
        }
    }
}

// ---------------- generic tiled SGEMM (64x64) ----------------
// AMODE 0: A[row*lda+k];  AMODE 1: A[gidx[row]*lda+k]  (row gather)
template<int AMODE,int BMODE,int ACT>
__global__ __launch_bounds__(256) void k_sgemm(
    const float* __restrict__ A, const int* __restrict__ gidx,
    const float* __restrict__ B, const float* __restrict__ B2,
    const float* __restrict__ bias, const float* __restrict__ bias2,
    float* __restrict__ C,
    int M, int N, int K, int lda, int ldbk, int ldbn, int ldc,
    long zA, long zB, long zC)
{
    const int BM=64, BN=64, BK=16;
    __shared__ float As[BK][BM+4];
    __shared__ float Bs[BK][BN+4];
    A += (long)blockIdx.z * zA;
    B += (long)blockIdx.z * zB;
    C += (long)blockIdx.z * zC;
    int bm = blockIdx.x*BM, bn = blockIdx.y*BN;
    int tid = threadIdx.x;
    int tx = tid & 15, ty = tid >> 4;
    float acc[4][4];
    #pragma unroll
    for (int i=0;i<4;i++)
        #pragma unroll
        for (int j=0;j<4;j++) acc[i][j]=0.f;

    for (int k0=0;k0<K;k0+=BK){
        #pragma unroll
        for (int t=0;t<4;t++){
            int i = tid + t*256;
            int m = i >> 4, kk = i & 15;
            int row = bm + m, k = k0 + kk;
            float v = 0.f;
            if (row < M && k < K){
                long ar = (AMODE==1) ? (long)gidx[row] : (long)row;
                v = A[ar*lda + k];
            }
            As[kk][m] = v;
            int kk2 = i >> 6, n = i & 63;
            int col = bn + n, k2 = k0 + kk2;
            float w = 0.f;
            if (col < N && k2 < K){
                if (BMODE==0) w = B[(long)k2*ldbk + (long)col*ldbn];
                else          w = (col < HD) ? B[(long)k2*HD + col]
                                             : B2[(long)k2*HD + (col-HD)];
            }
            Bs[kk2][n] = w;
        }
        __syncthreads();
        #pragma unroll
        for (int kk=0;kk<BK;kk++){
            float a0=As[kk][ty*4+0], a1=As[kk][ty*4+1], a2=As[kk][ty*4+2], a3=As[kk][ty*4+3];
            float b0=Bs[kk][tx*4+0], b1=Bs[kk][tx*4+1], b2=Bs[kk][tx*4+2], b3=Bs[kk][tx*4+3];
            acc[0][0]+=a0*b0; acc[0][1]+=a0*b1; acc[0][2]+=a0*b2; acc[0][3]+=a0*b3;
            acc[1][0]+=a1*b0; acc[1][1]+=a1*b1; acc[1][2]+=a1*b2; acc[1][3]+=a1*b3;
            acc[2][0]+=a2*b0; acc[2][1]+=a2*b1; acc[2][2]+=a2*b2; acc[2][3]+=a2*b3;
            acc[3][0]+=a3*b0; acc[3][1]+=a3*b1; acc[3][2]+=a3*b2; acc[3][3]+=a3*b3;
        }
        __syncthreads();
    }
    #pragma unroll
    for (int i=0;i<4;i++){
        int row = bm + ty*4 + i;
        if (row >= M) continue;
        #pragma unroll
        for (int j=0;j<4;j++){
            int col = bn + tx*4 + j;
            if (col >= N) continue;
            float v = acc[i][j];
            if (BMODE==1){ if (bias) v += (col < HD) ? bias[col] : bias2[col-HD]; }
            else if (bias)           v += bias[col];
            if (ACT==1) v = tanhf(v);
            if (ACT==2) v = fmaxf(v, 0.f);
            C[(long)row*ldc + col] = v;
        }
    }
}

// ---------------- GAT pipeline: CSR build (real edges only) ----------------
__global__ void k_init(){
    int i = blockIdx.x*blockDim.x + threadIdx.x;
    if (i < NN){ g_cnt[i] = 0; g_cur[i] = 0; }
    if (i == 0) g_off[NN] = EE;
}

__global__ void k_count(const int* __restrict__ ei){
    int i = blockIdx.x*blockDim.x + threadIdx.x;
    if (i < EE) atomicAdd(&g_cnt[ei[EE+i]], 1);
}

__global__ void k_scan(){
    __shared__ int sh[1024];
    int t = threadIdx.x;
    const int chunk = (NN + 1023) / 1024;
    int base = t * chunk;
    int s = 0;
    for (int i=0;i<chunk;i++){ int idx = base+i; if (idx < NN) s += g_cnt[idx]; }
    sh[t] = s; __syncthreads();
    for (int d=1; d<1024; d<<=1){
        int v = (t >= d) ? sh[t-d] : 0;
        __syncthreads();
        sh[t] += v;
        __syncthreads();
    }
    int run = sh[t] - s;
    for (int i=0;i<chunk;i++){
        int idx = base+i;
        if (idx < NN){ g_off[idx] = run; run += g_cnt[idx]; }
    }
}

__global__ void k_scatter(const int* __restrict__ ei){
    int i = blockIdx.x*blockDim.x + threadIdx.x;
    if (i >= EE) return;
    int src = ei[i], dst = ei[EE+i];
    int pos = g_off[dst] + atomicAdd(&g_cur[dst], 1);
    g_srcs[pos] = src;
}

// warp per dst node: online-softmax GAT aggregation (self loop analytic)
__global__ void k_aggf(const float* __restrict__ att, const float* __restrict__ gbias){
    int n = blockIdx.x*(blockDim.x>>5) + (threadIdx.x>>5);
    if (n >= NN) return;
    int lane = threadIdx.x & 31;
    float4 xs = *(const float4*)(g_xlr + (long)n*256 + lane*4);
    float4 xr = *(const float4*)(g_xlr + (long)n*256 + 128 + lane*4);
    float4 at = *(const float4*)(att + lane*4);

    float e = lrelu(xs.x+xr.x)*at.x + lrelu(xs.y+xr.y)*at.y
            + lrelu(xs.z+xr.z)*at.z + lrelu(xs.w+xr.w)*at.w;
    #pragma unroll
    for (int o=16;o;o>>=1) e += __shfl_xor_sync(0xffffffffu, e, o);
    float m = e, s = 1.f;
    float4 acc = xs;

    int s0 = g_off[n], s1 = g_off[n+1];
    if (s0 < s1){
        int i1 = min(s0+1, s1-1);
        float4 xva = *(const float4*)(g_xlr + (long)g_srcs[s0]*256 + lane*4);
        float4 xvb = *(const float4*)(g_xlr + (long)g_srcs[i1]*256 + lane*4);
        float ec = lrelu(xva.x+xr.x)*at.x + lrelu(xva.y+xr.y)*at.y
                 + lrelu(xva.z+xr.z)*at.z + lrelu(xva.w+xr.w)*at.w;
        #pragma unroll
        for (int o=16;o;o>>=1) ec += __shfl_xor_sync(0xffffffffu, ec, o);
        for (int j=s0; j<s1; j++){
            int jn = min(j+2, s1-1);
            float4 xvc = *(const float4*)(g_xlr + (long)g_srcs[jn]*256 + lane*4);
            float en = lrelu(xvb.x+xr.x)*at.x + lrelu(xvb.y+xr.y)*at.y
                     + lrelu(xvb.z+xr.z)*at.z + lrelu(xvb.w+xr.w)*at.w;
            #pragma unroll
            for (int o=16;o;o>>=1) en += __shfl_xor_sync(0xffffffffu, en, o);
            float mn = fmaxf(m, ec);
            float sc = __expf(m - mn);
            float w  = __expf(ec - mn);
            s = s*sc + w;
            acc.x = acc.x*sc + w*xva.x;
            acc.y = acc.y*sc + w*xva.y;
            acc.z = acc.z*sc + w*xva.z;
            acc.w = acc.w*sc + w*xva.w;
            m = mn;
            xva = xvb; xvb = xvc; ec = en;
        }
    }
    float inv = 1.f / s;
    float4 bv = *(const float4*)(gbias + lane*4);
    float* op = g_intra + (long)n*HD + lane*4;
    op[0] = tanhf(acc.x*inv + bv.x);
    op[1] = tanhf(acc.y*inv + bv.y);
    op[2] = tanhf(acc.z*inv + bv.z);
    op[3] = tanhf(acc.w*inv + bv.w);
}

// ---------------- fused attention consumer: softmax(scale*S) @ V, flash-style ----------------
// grid (GD/32, NH), 256 threads. Reads raw scores g_sc, V from g_qkv, writes g_o.
#define QB 32
__global__ __launch_bounds__(256) void k_attav(){
    __shared__ __align__(16) float Ps[QB][132];
    __shared__ __align__(16) float Vs[128][36];
    __shared__ float sm[QB], ss[QB], ssc[QB];
    const int h  = blockIdx.y;
    const int r0 = blockIdx.x * QB;
    const int tid = threadIdx.x, lane = tid & 31, w = tid >> 5;
    const float scale = 0.17677669529663687f;   // 1/sqrt(32)

    if (tid < QB){ sm[tid] = -1e30f; ss[tid] = 0.f; ssc[tid] = 0.f; }

    const int ar = tid >> 3;          // 0..31 (row)
    const int ad = (tid & 7) * 4;     // 0..28 (dim group)
    float4 acc = make_float4(0.f,0.f,0.f,0.f);

    for (int c = 0; c < GD/128; c++){
        __syncthreads();   // Ps/Vs reuse + stats visibility
        // load V chunk [128 keys][32 dims]
        {
            int key = tid >> 1;
            int dh  = (tid & 1) * 16;
            const float* vp = g_qkv + (long)(c*128+key)*(3*HD) + 2*HD + h*32 + dh;
            #pragma unroll
            for (int i=0;i<4;i++){
                float4 vv = *(const float4*)(vp + i*4);
                Vs[key][dh+i*4+0]=vv.x; Vs[key][dh+i*4+1]=vv.y;
                Vs[key][dh+i*4+2]=vv.z; Vs[key][dh+i*4+3]=vv.w;
            }
        }
        // score phase: warp w owns rows 4w..4w+4
        #pragma unroll
        for (int rr=0; rr<4; rr++){
            int r = w*4 + rr;
            const float* sp = g_sc + (long)h*GD*GD + (long)(r0+r)*GD + c*128 + lane*4;
            float4 sv = *(const float4*)sp;
            sv.x *= scale; sv.y *= scale; sv.z *= scale; sv.w *= scale;
            float mx = fmaxf(fmaxf(sv.x,sv.y), fmaxf(sv.z,sv.w));
            #pragma unroll
            for (int o=16;o;o>>=1) mx = fmaxf(mx, __shfl_xor_sync(0xffffffffu, mx, o));
            float mo = sm[r];
            float mn = fmaxf(mo, mx);
            float p0 = __expf(sv.x - mn), p1 = __expf(sv.y - mn);
            float p2 = __expf(sv.z - mn), p3 = __expf(sv.w - mn);
            *(float4*)&Ps[r][lane*4] = make_float4(p0,p1,p2,p3);
            float sum = p0+p1+p2+p3;
            #pragma unroll
            for (int o=16;o;o>>=1) sum += __shfl_xor_sync(0xffffffffu, sum, o);
            if (lane == 0){
                float sc = __expf(mo - mn);
                ssc[r] = sc;
                ss[r]  = ss[r]*sc + sum;
                sm[r]  = mn;
            }
        }
        __syncthreads();
        // AV update: acc = acc*scale_r + P[r][:] @ V[:][ad..ad+3]
        float sc = ssc[ar];
        acc.x *= sc; acc.y *= sc; acc.z *= sc; acc.w *= sc;
        #pragma unroll 4
        for (int j=0;j<128;j++){
            float p = Ps[ar][j];
            float4 v = *(const float4*)&Vs[j][ad];
            acc.x += p*v.x; acc.y += p*v.y; acc.z += p*v.z; acc.w += p*v.w;
        }
    }
    float inv = 1.f / ss[ar];
    float* op = g_o + (long)(r0+ar)*HD + h*32 + ad;
    *(float4*)op = make_float4(acc.x*inv, acc.y*inv, acc.z*inv, acc.w*inv);
}

// out = [tanh]( LN(x[gather] + y) * g + b ), warp per row of 128
template<int TANH>
__global__ void k_ln(const float* __restrict__ x, const int* __restrict__ xg,
                     const float* __restrict__ y,
                     const float* __restrict__ g, const float* __restrict__ b,
                     float* __restrict__ out, int rows){
    int r = blockIdx.x*(blockDim.x>>5) + (threadIdx.x>>5);
    if (r >= rows) return;
    int lane = threadIdx.x & 31;
    long rx = xg ? (long)xg[r] : (long)r;
    float4 xv = *(const float4*)(x + rx*HD + lane*4);
    float4 yv = *(const float4*)(y + (long)r*HD + lane*4);
    float v0 = xv.x+yv.x, v1 = xv.y+yv.y, v2 = xv.z+yv.z, v3 = xv.w+yv.w;
    float s = v0+v1+v2+v3;
    #pragma unroll
    for (int o=16;o;o>>=1) s += __shfl_xor_sync(0xffffffffu, s, o);
    float mu = s * (1.f/128.f);
    float d0=v0-mu, d1=v1-mu, d2=v2-mu, d3=v3-mu;
    float q = d0*d0 + d1*d1 + d2*d2 + d3*d3;
    #pragma unroll
    for (int o=16;o;o>>=1) q += __shfl_xor_sync(0xffffffffu, q, o);
    float rs = rsqrtf(q * (1.f/128.f) + 1e-5f);
    float4 gv = *(const float4*)(g + lane*4);
    float4 bv = *(const float4*)(b + lane*4);
    float o0 = d0*rs*gv.x + bv.x;
    float o1 = d1*rs*gv.y + bv.y;
    float o2 = d2*rs*gv.z + bv.z;
    float o3 = d3*rs*gv.w + bv.w;
    if (TANH){ o0=tanhf(o0); o1=tanhf(o1); o2=tanhf(o2); o3=tanhf(o3); }
    *(float4*)(out + (long)r*HD + lane*4) = make_float4(o0,o1,o2,o3);
}

// ---------------- final heads: warp per node ----------------
__global__ void k_heads(const float* __restrict__ aw2, const float* __restrict__ ab2,
                        const float* __restrict__ vw2, const float* __restrict__ vb2,
                        float* __restrict__ out){
    int n = blockIdx.x*(blockDim.x>>5) + (threadIdx.x>>5);
    if (n >= NN) return;
    int lane = threadIdx.x & 31;
    const float* hp = g_hid + (long)n*256;
    float4 ha = *(const float4*)(hp + lane*4);
    float l[AD];
    #pragma unroll
    for (int j=0;j<AD;j++){
        l[j] = ha.x*aw2[(lane*4+0)*AD+j] + ha.y*aw2[(lane*4+1)*AD+j]
             + ha.z*aw2[(lane*4+2)*AD+j] + ha.w*aw2[(lane*4+3)*AD+j];
    }
    #pragma unroll
    for (int j=0;j<AD;j++)
        #pragma unroll
        for (int o=16;o;o>>=1) l[j] += __shfl_xor_sync(0xffffffffu, l[j], o);
    float4 hv = *(const float4*)(hp + 128 + lane*4);
    float4 wv = *(const float4*)(vw2 + lane*4);
    float v = hv.x*wv.x + hv.y*wv.y + hv.z*wv.z + hv.w*wv.w;
    #pragma unroll
    for (int o=16;o;o>>=1) v += __shfl_xor_sync(0xffffffffu, v, o);
    if (lane == 0){
        float m = -1e30f;
        #pragma unroll
        for (int j=0;j<AD;j++){ l[j] += ab2[j]; m = fmaxf(m, l[j]); }
        float s = 0.f;
        #pragma unroll
        for (int j=0;j<AD;j++) s += expf(l[j]-m);
        float ls = logf(s) + m;
        #pragma unroll
        for (int j=0;j<AD;j++) out[(long)n*AD + j] = l[j] - ls;
        out[(long)NN*AD + n] = v + vb2[0];
    }
}

// ---------------- host ----------------
extern "C" void kernel_launch(void* const* d_in, const int* in_sizes, int n_in,
                              void* d_out, int out_size)
{
    const float* obs  = (const float*)d_in[0];
    const int*   ei   = (const int*)d_in[1];
    const int*   ga   = (const int*)d_in[2];
    const int*   cn   = (const int*)d_in[3];
    const float* embw = (const float*)d_in[4];  const float* embb = (const float*)d_in[5];
    const float* wl   = (const float*)d_in[6];  const float* wr   = (const float*)d_in[7];
    const float* att  = (const float*)d_in[8];  const float* gbias= (const float*)d_in[9];
    const float* ainw = (const float*)d_in[10]; const float* ainb = (const float*)d_in[11];
    const float* aow  = (const float*)d_in[12]; const float* aob  = (const float*)d_in[13];
    const float* ln1g = (const float*)d_in[14]; const float* ln1b = (const float*)d_in[15];
    const float* ln2g = (const float*)d_in[16]; const float* ln2b = (const float*)d_in[17];
    const float* fw1  = (const float*)d_in[18]; const float* fb1  = (const float*)d_in[19];
    const float* fw2  = (const float*)d_in[20]; const float* fb2  = (const float*)d_in[21];
    const float* aw1  = (const float*)d_in[22]; const float* ab1  = (const float*)d_in[23];
    const float* aw2  = (const float*)d_in[24]; const float* ab2  = (const float*)d_in[25];
    const float* vw1  = (const float*)d_in[26]; const float* vb1  = (const float*)d_in[27];
    const float* vw2  = (const float*)d_in[28]; const float* vb2  = (const float*)d_in[29];
    float* out = (float*)d_out;

    void *pv;
    cudaGetSymbolAddress(&pv, g_x);     float* fx    = (float*)pv;
    cudaGetSymbolAddress(&pv, g_xlr);   float* fxlr  = (float*)pv;
    cudaGetSymbolAddress(&pv, g_intra); float* fintra= (float*)pv;
    cudaGetSymbolAddress(&pv, g_hid);   float* fhid  = (float*)pv;
    cudaGetSymbolAddress(&pv, g_qkv);   float* fqkv  = (float*)pv;
    cudaGetSymbolAddress(&pv, g_sc);    float* fsc   = (float*)pv;
    cudaGetSymbolAddress(&pv, g_o);     float* fo    = (float*)pv;
    cudaGetSymbolAddress(&pv, g_t1);    float* ft1   = (float*)pv;
    cudaGetSymbolAddress(&pv, g_h1);    float* fh1   = (float*)pv;
    cudaGetSymbolAddress(&pv, g_f);     float* ff    = (float*)pv;
    cudaGetSymbolAddress(&pv, g_gobs);  float* fgobs = (float*)pv;
    cudaGetSymbolAddress(&pv, g_pg);    float* fpg   = (float*)pv;

    static cudaStream_t s2 = nullptr;
    static cudaEvent_t evF = nullptr, evJ = nullptr;
    if (!s2){
        cudaStreamCreateWithFlags(&s2, cudaStreamNonBlocking);
        cudaEventCreateWithFlags(&evF, cudaEventDisableTiming);
        cudaEventCreateWithFlags(&evJ, cudaEventDisableTiming);
    }

    const int GB = (NN + 127) / 128;

    // ---- fork: CSR build on s2, overlapping the big GEMMs on the main stream ----
    cudaEventRecord(evF, 0);
    cudaStreamWaitEvent(s2, evF, 0);
    k_init   <<<(NN+255)/256, 256, 0, s2>>>();
    k_count  <<<(EE+255)/256, 256, 0, s2>>>(ei);
    k_scan   <<<1, 1024, 0, s2>>>();
    k_scatter<<<(EE+255)/256, 256, 0, s2>>>(ei);
    cudaEventRecord(evJ, s2);

    // x = tanh(obs @ emb_w + b)
    k_tgemm<1><<<dim3(GB,1),256>>>(obs, embw,nullptr, embb,nullptr, nullptr,nullptr,
                                   fx, NN, OBSD, OBSD, HD);
    // [xl|xr] = x @ [Wl|Wr]
    k_tgemm<0><<<dim3(GB,2),256>>>(fx, wl,wr, nullptr,nullptr, nullptr,nullptr,
                                   fxlr, NN, HD, HD, 2*HD);

    // ---- join: aggregation needs both the CSR and xlr ----
    cudaStreamWaitEvent(0, evJ, 0);
    k_aggf<<<(NN+7)/8, 256>>>(att, gbias);

    // transformer over core nodes (c-rows gathered by cn directly in the GEMM)
    dim3 g3((GD+63)/64, (3*HD+63)/64);
    k_sgemm<1,0,0><<<g3,256>>>(fintra, cn, ainw,nullptr, ainb,nullptr,
                               fqkv, GD,3*HD,HD, HD,3*HD,1,3*HD, 0,0,0);
    // raw scores[h] = Q_h @ K_h^T
    dim3 g4((GD+63)/64, (GD+63)/64, 4);
    k_sgemm<0,0,0><<<g4,256>>>(fqkv, nullptr, fqkv+HD,nullptr, nullptr,nullptr,
                               fsc, GD,GD,32, 3*HD,1,3*HD,GD, 32,32,(long)GD*GD);
    // fused softmax + AV
    k_attav<<<dim3(GD/QB, NH), 256>>>();
    // out-proj, LN1 (residual gathers intra[cn]), FFN, LN2+tanh
    dim3 g6((GD+63)/64, (HD+63)/64);
    k_sgemm<0,0,0><<<g6,256>>>(fo, nullptr, aow,nullptr, aob,nullptr,
                               ft1, GD,HD,HD, HD,HD,1,HD, 0,0,0);
    k_ln<0><<<(GD+7)/8, 256>>>(fintra, cn, ft1, ln1g, ln1b, fh1, GD);
    k_sgemm<0,0,2><<<g6,256>>>(fh1, nullptr, fw1,nullptr, fb1,nullptr,
                               ff, GD,HD,HD, HD,HD,1,HD, 0,0,0);
    k_sgemm<0,0,0><<<g6,256>>>(ff, nullptr, fw2,nullptr, fb2,nullptr,
                               ft1, GD,HD,HD, HD,HD,1,HD, 0,0,0);
    k_ln<1><<<(GD+7)/8, 256>>>(fh1, nullptr, ft1, ln2g, ln2b, fgobs, GD);

    // PG = gobs @ [actor_w1_top | value_w1_top]
    dim3 g8((GD+63)/64, (2*HD+63)/64);
    k_sgemm<0,1,0><<<g8,256>>>(fgobs, nullptr, aw1,vw1, nullptr,nullptr,
                               fpg, GD,2*HD,HD, HD,0,0,2*HD, 0,0,0);
    // hidden = tanh( intra @ [actor_w1_bot | value_w1_bot] + bias + PG[ga] )
    k_tgemm<3><<<dim3(GB,2),256>>>(fintra, aw1 + HD*HD, vw1 + HD*HD, ab1, vb1,
                                   fpg, ga, fhid, NN, HD, HD, 2*HD);
    // final logits + log_softmax + value
    k_heads<<<(NN+7)/8, 256>>>(aw2, ab2, vw2, vb2, out);
}